// round 9
// baseline (speedup 1.0000x reference)
#include <cuda_runtime.h>

#define TT 150
#define VV 2048
#define CC 16
#define LL 64
#define EE 32768
#define NV 16384
#define L3 192

typedef unsigned long long u64;

__device__ float g_xe[(size_t)TT * NV * LL];
__device__ float g_agg[(size_t)TT * NV * LL];
__device__ float g_hd[NV * LL];
__device__ float g_pre[NV * LL];
__device__ float g_Wgdi[LL * L3];
__device__ float g_Wgci[LL * L3];
__device__ int   g_off[VV + 1];
__device__ int   g_eid[EE];

__device__ __forceinline__ u64 pk2(float x, float y) {
    u64 r; asm("mov.b64 %0, {%1, %2};" : "=l"(r) : "f"(x), "f"(y)); return r;
}
__device__ __forceinline__ void upk2(u64 v, float& x, float& y) {
    asm("mov.b64 {%0, %1}, %2;" : "=f"(x), "=f"(y) : "l"(v));
}
__device__ __forceinline__ void fma2(u64& d, u64 a, u64 b) {
    asm("fma.rn.f32x2 %0, %1, %2, %0;" : "+l"(d) : "l"(a), "l"(b));
}
__device__ __forceinline__ float hadd2(u64 v) { float x, y; upk2(v, x, y); return x + y; }
__device__ __forceinline__ float sigf(float x) {
    x = fminf(fmaxf(x, -20.f), 20.f);
    return __fdividef(1.f, 1.f + __expf(-x));
}
__device__ __forceinline__ float tanh_f(float x) {
    x = fminf(fmaxf(x, -10.f), 10.f);
    float e = __expf(-2.f * x);
    return __fdividef(1.f - e, 1.f + e);
}

// ---------------- encoder ----------------
__global__ void __launch_bounds__(256) k_enc(const float* __restrict__ x,
                                             const float* __restrict__ Wenc,
                                             const float* __restrict__ benc) {
    __shared__ float sx[CC * TT];
    __shared__ float2 sW[CC * 32];
    __shared__ float2 sb[32];
    int tid = threadIdx.x, r = blockIdx.x;
    for (int i = tid; i < CC * TT; i += 256) sx[i] = x[(size_t)r * CC * TT + i];
    for (int i = tid; i < CC * 32; i += 256) {
        int c = i >> 5, l = i & 31;
        sW[i] = make_float2(Wenc[c * LL + l], Wenc[c * LL + l + 32]);
    }
    if (tid < 32) sb[tid] = make_float2(benc[tid], benc[tid + 32]);
    __syncthreads();
    int wid = tid >> 5, lane = tid & 31;
    for (int t = wid; t < TT; t += 8) {
        u64 acc = pk2(sb[lane].x, sb[lane].y);
        #pragma unroll
        for (int c = 0; c < CC; c++) {
            float xs = sx[c * TT + t];
            fma2(acc, pk2(xs, xs), pk2(sW[c * 32 + lane].x, sW[c * 32 + lane].y));
        }
        float ax, ay; upk2(acc, ax, ay);
        size_t o = ((size_t)t * NV + r) * LL;
        g_xe[o + lane] = ax;
        g_xe[o + lane + 32] = ay;
    }
}

// ---------------- fused CSR build + weight combines ----------------
__global__ void __launch_bounds__(1024) k_csr(const int* __restrict__ ei,
        const float* __restrict__ Wgd, const float* __restrict__ gdWi,
        const float* __restrict__ Wgc, const float* __restrict__ gcWi) {
    __shared__ int scnt[VV];
    __shared__ int sfil[VV];
    int tid = threadIdx.x;
    for (int i = tid; i < VV; i += 1024) { scnt[i] = 0; sfil[i] = 0; }
    __syncthreads();
    for (int e = tid; e < EE; e += 1024) atomicAdd(&scnt[ei[EE + e]], 1);
    __syncthreads();
    if (tid == 0) {
        int acc = 0;
        for (int v = 0; v < VV; v++) { g_off[v] = acc; acc += scnt[v]; }
        g_off[VV] = acc;
    }
    __syncthreads();
    for (int e = tid; e < EE; e += 1024) {
        int d = ei[EE + e];
        int p = g_off[d] + atomicAdd(&sfil[d], 1);
        g_eid[p] = e;
    }
    __syncthreads();
    for (int v = tid; v < VV; v += 1024) {
        int s = g_off[v], en = g_off[v + 1];
        for (int i = s + 1; i < en; i++) {
            int key = g_eid[i];
            int j = i - 1;
            while (j >= s && g_eid[j] > key) { g_eid[j + 1] = g_eid[j]; j--; }
            g_eid[j + 1] = key;
        }
    }
    for (int idx = tid; idx < 2 * LL * L3; idx += 1024) {
        int which = idx >= LL * L3;
        int rem = which ? idx - LL * L3 : idx;
        int k = rem / L3, j = rem - k * L3;
        const float* A = which ? Wgc : Wgd;
        const float* B = which ? gcWi : gdWi;
        float acc = 0.f;
        #pragma unroll 8
        for (int m = 0; m < LL; m++) acc = fmaf(A[k * LL + m], B[m * L3 + j], acc);
        (which ? g_Wgci : g_Wgdi)[rem] = acc;
    }
}

// ---------------- aggregation ----------------
__global__ void __launch_bounds__(256) k_agg(const int* __restrict__ ei,
                                             const float* __restrict__ attr) {
    int tid = threadIdx.x, wid = tid >> 5, lane = tid & 31;
    int gw = blockIdx.x * 8 + wid, nw = gridDim.x * 8;
    for (int task = gw; task < TT * NV; task += nw) {
        int t = task >> 14;
        int r = task & (NV - 1);
        int v = r & (VV - 1);
        const float* xb = g_xe + ((size_t)t * NV + (r & ~(VV - 1))) * LL;
        int s0 = g_off[v], s1 = g_off[v + 1];
        u64 acc = 0ULL;
        for (int e = s0; e < s1; e++) {
            int id = g_eid[e];
            int s = ei[id];
            float w = attr[id];
            float2 vv = ((const float2*)(xb + (size_t)s * LL))[lane];
            fma2(acc, pk2(w, w), pk2(vv.x, vv.y));
        }
        float a0, a1; upk2(acc, a0, a1);
        ((float2*)(g_agg + (size_t)task * LL))[lane] = make_float2(a0, a1);
    }
}

// ---------------- scan1: GEMM-style persistent domain GRU (no shuffles) ----------------
// A-tile [64 rows][agg 64 | h 64], padded stride 132 f (33 ull2).
// Wzr [128 cols (z,r)][128 k (agg|h)], stride 132 f. Wni/Wnh [64 c][64 k], stride 68 f.
#define AS 132
#define WS 132
#define NS 68
__global__ void __launch_bounds__(256, 1) k_scan1(const float* __restrict__ Wh,
                                                  const float* __restrict__ bg) {
    extern __shared__ float sm1[];
    float* sWzr = sm1;                       // 128*132
    float* sWni = sWzr + 128 * WS;           // 64*68
    float* sWnh = sWni + 64 * NS;            // 64*68
    float* sA   = sWnh + 64 * NS;            // 64*132
    float* sb   = sA + 64 * AS;              // 192
    int tid = threadIdx.x;
    for (int i = tid; i < 128 * 128; i += 256) {
        int c = i >> 7, k = i & 127;
        int g = c >> 6, cc = c & 63;
        sWzr[c * WS + k] = (k < 64) ? g_Wgdi[k * L3 + g * 64 + cc]
                                    : Wh[(k - 64) * L3 + g * 64 + cc];
    }
    for (int i = tid; i < 64 * 64; i += 256) {
        int c = i >> 6, k = i & 63;
        sWni[c * NS + k] = g_Wgdi[k * L3 + 128 + c];
        sWnh[c * NS + k] = Wh[k * L3 + 128 + c];
    }
    if (tid < 192) sb[tid] = bg[tid];
    for (int i = tid; i < 64 * 64; i += 256) sA[(i >> 6) * AS + 64 + (i & 63)] = 0.f;
    __syncthreads();
    int rg = tid >> 4, ct = tid & 15;        // 16 rowgroups x 4 rows; 16 colthreads
    int r0 = blockIdx.x * 64;
    const ulonglong2* At = (const ulonglong2*)sA;          // row stride 33
    const ulonglong2* Wz = (const ulonglong2*)sWzr;        // col stride 33
    const ulonglong2* Ni = (const ulonglong2*)sWni;        // col stride 17
    const ulonglong2* Nh = (const ulonglong2*)sWnh;
    for (int t = 0; t < TT; t++) {
        // stage agg[t] slice (64 rows x 16 float4)
        const float4* src = (const float4*)(g_agg + ((size_t)t * NV + r0) * LL);
        for (int i = tid; i < 1024; i += 256) {
            int row = i >> 4, q = i & 15;
            ((float4*)sA)[row * 33 + q] = src[row * 16 + q];
        }
        __syncthreads();
        u64 zr[8][4], ni[4][4], nh[4][4];
        #pragma unroll
        for (int j = 0; j < 8; j++)
            #pragma unroll
            for (int r = 0; r < 4; r++) zr[j][r] = 0ULL;
        #pragma unroll
        for (int j = 0; j < 4; j++)
            #pragma unroll
            for (int r = 0; r < 4; r++) { ni[j][r] = 0ULL; nh[j][r] = 0ULL; }
        // loop1: k 0..63 (agg half)
        #pragma unroll 4
        for (int kb = 0; kb < 16; kb++) {
            ulonglong2 a[4];
            #pragma unroll
            for (int r = 0; r < 4; r++) a[r] = At[(rg * 4 + r) * 33 + kb];
            #pragma unroll
            for (int j = 0; j < 8; j++) {
                ulonglong2 w = Wz[(ct + 16 * j) * 33 + kb];
                #pragma unroll
                for (int r = 0; r < 4; r++) { fma2(zr[j][r], a[r].x, w.x); fma2(zr[j][r], a[r].y, w.y); }
            }
            #pragma unroll
            for (int j = 0; j < 4; j++) {
                ulonglong2 w = Ni[(ct + 16 * j) * 17 + kb];
                #pragma unroll
                for (int r = 0; r < 4; r++) { fma2(ni[j][r], a[r].x, w.x); fma2(ni[j][r], a[r].y, w.y); }
            }
        }
        // loop2: k 64..127 (h half)
        #pragma unroll 4
        for (int kb = 0; kb < 16; kb++) {
            ulonglong2 a[4];
            #pragma unroll
            for (int r = 0; r < 4; r++) a[r] = At[(rg * 4 + r) * 33 + 16 + kb];
            #pragma unroll
            for (int j = 0; j < 8; j++) {
                ulonglong2 w = Wz[(ct + 16 * j) * 33 + 16 + kb];
                #pragma unroll
                for (int r = 0; r < 4; r++) { fma2(zr[j][r], a[r].x, w.x); fma2(zr[j][r], a[r].y, w.y); }
            }
            #pragma unroll
            for (int j = 0; j < 4; j++) {
                ulonglong2 w = Nh[(ct + 16 * j) * 17 + kb];
                #pragma unroll
                for (int r = 0; r < 4; r++) { fma2(nh[j][r], a[r].x, w.x); fma2(nh[j][r], a[r].y, w.y); }
            }
        }
        // gates + h' (h' for cols ct+16j, j=0..3, rows rg*4..+3)
        float hn[4][4];
        #pragma unroll
        for (int j = 0; j < 4; j++) {
            int cj = ct + 16 * j;
            #pragma unroll
            for (int r = 0; r < 4; r++) {
                int row = rg * 4 + r;
                float z = sigf(hadd2(zr[j][r]) + sb[cj]);
                float rr = sigf(hadd2(zr[j + 4][r]) + sb[64 + cj]);
                float n = tanh_f(hadd2(ni[j][r]) + sb[128 + cj] + rr * hadd2(nh[j][r]));
                float hold = sA[row * AS + 64 + cj];
                hn[j][r] = (1.f - z) * n + z * hold;
            }
        }
        __syncthreads();
        #pragma unroll
        for (int j = 0; j < 4; j++)
            #pragma unroll
            for (int r = 0; r < 4; r++)
                sA[(rg * 4 + r) * AS + 64 + ct + 16 * j] = hn[j][r];
        __syncthreads();
    }
    for (int i = tid; i < 64 * 64; i += 256) {
        int row = i >> 6, c = i & 63;
        g_hd[(size_t)(r0 + row) * LL + c] = sA[row * AS + 64 + c];
    }
}

// ---------------- z_D + pre_ode ----------------
__global__ void __launch_bounds__(256) k_zd(const float* __restrict__ Wd1, const float* __restrict__ bd1,
                                            const float* __restrict__ Wd2, const float* __restrict__ bd2,
                                            const float* __restrict__ oW1, const float* __restrict__ ob1) {
    extern __shared__ u64 smz[];
    u64* sA = smz;
    u64* sB = sA + 2048;
    u64* sC = sB + 2048;
    u64* b1 = sC + 2048;
    u64* b2 = b1 + 32;
    u64* b3 = b2 + 32;
    int tid = threadIdx.x;
    for (int i = tid; i < 2048; i += 256) {
        int k = i >> 5, l = i & 31;
        sA[i] = pk2(Wd1[k * 64 + l], Wd1[k * 64 + l + 32]);
        sB[i] = pk2(Wd2[k * 64 + l], Wd2[k * 64 + l + 32]);
        sC[i] = pk2(oW1[(64 + k) * 64 + l], oW1[(64 + k) * 64 + l + 32]);
    }
    if (tid < 32) {
        b1[tid] = pk2(bd1[tid], bd1[tid + 32]);
        b2[tid] = pk2(bd2[tid], bd2[tid + 32]);
        b3[tid] = pk2(ob1[tid], ob1[tid + 32]);
    }
    __syncthreads();
    int wid = tid >> 5, lane = tid & 31;
    for (int r = blockIdx.x * 8 + wid; r < NV; r += gridDim.x * 8) {
        size_t o = (size_t)r * LL + lane;
        float2 hd = make_float2(g_hd[o], g_hd[o + 32]);
        u64 u = b1[lane];
        #pragma unroll
        for (int half = 0; half < 2; half++)
            #pragma unroll 8
            for (int kk = 0; kk < 32; kk++) {
                float hv = __shfl_sync(0xffffffffu, half ? hd.y : hd.x, kk);
                fma2(u, pk2(hv, hv), sA[(half * 32 + kk) * 32 + lane]);
            }
        float ux, uy; upk2(u, ux, uy);
        float2 uf = make_float2(tanh_f(ux), tanh_f(uy));
        u64 v = b2[lane];
        #pragma unroll
        for (int half = 0; half < 2; half++)
            #pragma unroll 8
            for (int kk = 0; kk < 32; kk++) {
                float uv = __shfl_sync(0xffffffffu, half ? uf.y : uf.x, kk);
                fma2(v, pk2(uv, uv), sB[(half * 32 + kk) * 32 + lane]);
            }
        float vx, vy; upk2(v, vx, vy);
        float2 vf = make_float2(vx, vy);
        u64 p = b3[lane];
        #pragma unroll
        for (int half = 0; half < 2; half++)
            #pragma unroll 8
            for (int kk = 0; kk < 32; kk++) {
                float vv = __shfl_sync(0xffffffffu, half ? vf.y : vf.x, kk);
                fma2(p, pk2(vv, vv), sC[(half * 32 + kk) * 32 + lane]);
            }
        float px, py; upk2(p, px, py);
        g_pre[o] = px;
        g_pre[o + 32] = py;
    }
}

// ---------------- persistent main scan (unchanged R8 structure) ----------------
__global__ void __launch_bounds__(512, 1) k_scan2(
        const float* __restrict__ Wh, const float* __restrict__ bg,
        const float* __restrict__ oW1, const float* __restrict__ oW2,
        const float* __restrict__ ob2,
        const float* __restrict__ Wdec, const float* __restrict__ bdec,
        float* __restrict__ out) {
    extern __shared__ char sms[];
    u64*   sWi  = (u64*)sms;
    u64*   sWhp = (u64*)(sms + 49152);
    u64*   sW1  = (u64*)(sms + 98304);
    u64*   sW2  = (u64*)(sms + 114688);
    float* sWdc = (float*)(sms + 131072);
    u64*   sbg  = (u64*)(sms + 135168);
    u64*   sb2  = (u64*)(sms + 135936);
    float* sbd  = (float*)(sms + 136192);
    float* srow = (float*)(sms + 136256);
    int tid = threadIdx.x;
    for (int i = tid; i < 6144; i += 512) {
        int k = i / 96, u = i - k * 96, g = u >> 5, l = u & 31;
        sWi[i]  = pk2(g_Wgci[k * L3 + g * 64 + l], g_Wgci[k * L3 + g * 64 + l + 32]);
        sWhp[i] = pk2(Wh[k * L3 + g * 64 + l], Wh[k * L3 + g * 64 + l + 32]);
    }
    for (int i = tid; i < 2048; i += 512) {
        int k = i >> 5, l = i & 31;
        sW1[i] = pk2(oW1[k * 64 + l], oW1[k * 64 + l + 32]);
        sW2[i] = pk2(oW2[k * 64 + l], oW2[k * 64 + l + 32]);
    }
    for (int i = tid; i < 1024; i += 512) sWdc[i] = Wdec[i];
    if (tid < 96) {
        int g = tid >> 5, l = tid & 31;
        sbg[tid] = pk2(bg[g * 64 + l], bg[g * 64 + l + 32]);
    }
    if (tid < 32) sb2[tid] = pk2(ob2[tid], ob2[tid + 32]);
    if (tid < 16) sbd[tid] = bdec[tid];
    __syncthreads();
    int wid = tid >> 5, lane = tid & 31;
    int c = lane & 15, hf = lane >> 4;
    for (int task = blockIdx.x * 16 + wid; task < NV / 4; task += gridDim.x * 16) {
        int r0 = task << 2;
        float2 h[4];
        u64 pre[4];
        #pragma unroll
        for (int i = 0; i < 4; i++) {
            size_t o = (size_t)(r0 + i) * LL + lane;
            h[i] = make_float2(g_xe[o], g_xe[o + 32]);
            pre[i] = pk2(g_pre[o], g_pre[o + 32]);
        }
        #pragma unroll
        for (int i = 0; i < 4; i++) {
            srow[wid * LL + lane] = h[i].x;
            srow[wid * LL + lane + 32] = h[i].y;
            __syncwarp();
            float acc = 0.f;
            #pragma unroll
            for (int j = 0; j < 32; j++) {
                int l = (hf << 5) + j;
                acc = fmaf(srow[wid * LL + l], sWdc[l * CC + c], acc);
            }
            acc += __shfl_xor_sync(0xffffffffu, acc, 16);
            if (lane < 16) out[((size_t)(r0 + i) * CC + c) * TT] = acc + sbd[c];
            __syncwarp();
        }
        for (int t = 1; t < TT; t++) {
            u64 u[4];
            #pragma unroll
            for (int i = 0; i < 4; i++) u[i] = pre[i];
            #pragma unroll
            for (int half = 0; half < 2; half++)
                #pragma unroll 8
                for (int kk = 0; kk < 32; kk++) {
                    u64 w = sW1[(half * 32 + kk) * 32 + lane];
                    #pragma unroll
                    for (int i = 0; i < 4; i++) {
                        float hv = __shfl_sync(0xffffffffu, half ? h[i].y : h[i].x, kk);
                        fma2(u[i], pk2(hv, hv), w);
                    }
                }
            float2 uf[4];
            #pragma unroll
            for (int i = 0; i < 4; i++) {
                float ux, uy; upk2(u[i], ux, uy);
                uf[i] = make_float2(tanh_f(ux), tanh_f(uy));
            }
            u64 d[4];
            #pragma unroll
            for (int i = 0; i < 4; i++) d[i] = sb2[lane];
            #pragma unroll
            for (int half = 0; half < 2; half++)
                #pragma unroll 8
                for (int kk = 0; kk < 32; kk++) {
                    u64 w = sW2[(half * 32 + kk) * 32 + lane];
                    #pragma unroll
                    for (int i = 0; i < 4; i++) {
                        float uv = __shfl_sync(0xffffffffu, half ? uf[i].y : uf[i].x, kk);
                        fma2(d[i], pk2(uv, uv), w);
                    }
                }
            float2 ho[4], a2[4];
            #pragma unroll
            for (int i = 0; i < 4; i++) {
                float dx, dy; upk2(d[i], dx, dy);
                ho[i] = make_float2(h[i].x + dx, h[i].y + dy);
                size_t o = ((size_t)t * NV + r0 + i) * LL + lane;
                a2[i] = make_float2(g_agg[o], g_agg[o + 32]);
            }
            u64 gi[4][3], gh[4][3];
            #pragma unroll
            for (int i = 0; i < 4; i++)
                #pragma unroll
                for (int g = 0; g < 3; g++) { gi[i][g] = sbg[g * 32 + lane]; gh[i][g] = 0ULL; }
            #pragma unroll
            for (int half = 0; half < 2; half++) {
                #pragma unroll 8
                for (int kk = 0; kk < 32; kk++) {
                    int k = half * 32 + kk;
                    u64 hb[4], ab[4];
                    #pragma unroll
                    for (int i = 0; i < 4; i++) {
                        float hv = __shfl_sync(0xffffffffu, half ? ho[i].y : ho[i].x, kk);
                        float av = __shfl_sync(0xffffffffu, half ? a2[i].y : a2[i].x, kk);
                        hb[i] = pk2(hv, hv);
                        ab[i] = pk2(av, av);
                    }
                    #pragma unroll
                    for (int g = 0; g < 3; g++) {
                        u64 wi = sWi[k * 96 + g * 32 + lane];
                        u64 wv = sWhp[k * 96 + g * 32 + lane];
                        #pragma unroll
                        for (int i = 0; i < 4; i++) { fma2(gi[i][g], ab[i], wi); fma2(gh[i][g], hb[i], wv); }
                    }
                }
            }
            #pragma unroll
            for (int i = 0; i < 4; i++) {
                float zx, zy, rx, ry, nix, niy, nhx, nhy;
                upk2(gi[i][0], zx, zy); upk2(gh[i][0], nix, niy);
                zx = sigf(zx + nix); zy = sigf(zy + niy);
                upk2(gi[i][1], rx, ry); upk2(gh[i][1], nix, niy);
                rx = sigf(rx + nix); ry = sigf(ry + niy);
                upk2(gi[i][2], nix, niy); upk2(gh[i][2], nhx, nhy);
                float nx = tanh_f(nix + rx * nhx), ny = tanh_f(niy + ry * nhy);
                h[i].x = (1.f - zx) * nx + zx * ho[i].x;
                h[i].y = (1.f - zy) * ny + zy * ho[i].y;
                srow[wid * LL + lane] = h[i].x;
                srow[wid * LL + lane + 32] = h[i].y;
                __syncwarp();
                float acc = 0.f;
                #pragma unroll
                for (int j = 0; j < 32; j++) {
                    int l = (hf << 5) + j;
                    acc = fmaf(srow[wid * LL + l], sWdc[l * CC + c], acc);
                }
                acc += __shfl_xor_sync(0xffffffffu, acc, 16);
                if (lane < 16) out[((size_t)(r0 + i) * CC + c) * TT + t] = acc + sbd[c];
                __syncwarp();
            }
        }
    }
}

// ---------------- launcher ----------------
extern "C" void kernel_launch(void* const* d_in, const int* in_sizes, int n_in,
                              void* d_out, int out_size) {
    const float* x    = (const float*)d_in[0];
    const int*   ei   = (const int*)d_in[1];
    const float* attr = (const float*)d_in[2];
    const float* Wenc = (const float*)d_in[3];
    const float* benc = (const float*)d_in[4];
    const float* Wgd  = (const float*)d_in[5];
    const float* gdWi = (const float*)d_in[6];
    const float* gdWh = (const float*)d_in[7];
    const float* gdb  = (const float*)d_in[8];
    const float* Wd1  = (const float*)d_in[9];
    const float* bd1  = (const float*)d_in[10];
    const float* Wd2  = (const float*)d_in[11];
    const float* bd2  = (const float*)d_in[12];
    const float* oW1  = (const float*)d_in[13];
    const float* ob1  = (const float*)d_in[14];
    const float* oW2  = (const float*)d_in[15];
    const float* ob2  = (const float*)d_in[16];
    const float* Wgc  = (const float*)d_in[17];
    const float* gcWi = (const float*)d_in[18];
    const float* gcWh = (const float*)d_in[19];
    const float* gcb  = (const float*)d_in[20];
    const float* Wdec = (const float*)d_in[21];
    const float* bdec = (const float*)d_in[22];
    float* out = (float*)d_out;

    int s1 = (128 * WS + 2 * 64 * NS + 64 * AS + 192) * 4;   // ~137 KB
    cudaFuncSetAttribute(k_scan1, cudaFuncAttributeMaxDynamicSharedMemorySize, s1);
    cudaFuncSetAttribute(k_zd,    cudaFuncAttributeMaxDynamicSharedMemorySize, 49920);
    cudaFuncSetAttribute(k_scan2, cudaFuncAttributeMaxDynamicSharedMemorySize, 140352);

    k_enc<<<NV, 256>>>(x, Wenc, benc);                               // 0
    k_csr<<<1, 1024>>>(ei, Wgd, gdWi, Wgc, gcWi);                    // 1
    k_agg<<<4096, 256>>>(ei, attr);                                  // 2
    k_scan1<<<256, 256, s1>>>(gdWh, gdb);                            // 3 <- ncu capture slot
    k_zd<<<128, 256, 49920>>>(Wd1, bd1, Wd2, bd2, oW1, ob1);         // 4
    k_scan2<<<148, 512, 140352>>>(gcWh, gcb, oW1, oW2, ob2, Wdec, bdec, out);  // 5
}

// round 11
// speedup vs baseline: 1.2386x; 1.2386x over previous
#include <cuda_runtime.h>
#include <cuda_bf16.h>

#define TT 150
#define VV 2048
#define CC 16
#define LL 64
#define EE 32768
#define NV 16384
#define L3 192

typedef unsigned long long u64;
typedef unsigned int u32;

__device__ float g_xe[(size_t)TT * NV * LL];
__device__ float g_agg[(size_t)TT * NV * LL];
__device__ float g_hd[NV * LL];
__device__ float g_pre[NV * LL];
__device__ float g_Wgdi[LL * L3];
__device__ float g_Wgci[LL * L3];
__device__ int   g_off[VV + 1];
__device__ int   g_eid[EE];

__device__ __forceinline__ u64 pk2(float x, float y) {
    u64 r; asm("mov.b64 %0, {%1, %2};" : "=l"(r) : "f"(x), "f"(y)); return r;
}
__device__ __forceinline__ void upk2(u64 v, float& x, float& y) {
    asm("mov.b64 {%0, %1}, %2;" : "=f"(x), "=f"(y) : "l"(v));
}
__device__ __forceinline__ void fma2(u64& d, u64 a, u64 b) {
    asm("fma.rn.f32x2 %0, %1, %2, %0;" : "+l"(d) : "l"(a), "l"(b));
}
__device__ __forceinline__ float sigf(float x) {
    x = fminf(fmaxf(x, -20.f), 20.f);
    return __fdividef(1.f, 1.f + __expf(-x));
}
__device__ __forceinline__ float tanh_f(float x) {
    x = fminf(fmaxf(x, -10.f), 10.f);
    float e = __expf(-2.f * x);
    return __fdividef(1.f - e, 1.f + e);
}
__device__ __forceinline__ void bfsplit(float x, u32& hb, u32& lb) {
    __nv_bfloat16 h = __float2bfloat16(x);
    __nv_bfloat16 l = __float2bfloat16(x - __bfloat162float(h));
    hb = (u32)__bfloat16_as_ushort(h);
    lb = (u32)__bfloat16_as_ushort(l);
}
__device__ __forceinline__ void mma16816(float* c, const u32* a, const u32* b) {
    asm volatile("mma.sync.aligned.m16n8k16.row.col.f32.bf16.bf16.f32 "
        "{%0,%1,%2,%3}, {%4,%5,%6,%7}, {%8,%9}, {%0,%1,%2,%3};"
        : "+f"(c[0]), "+f"(c[1]), "+f"(c[2]), "+f"(c[3])
        : "r"(a[0]), "r"(a[1]), "r"(a[2]), "r"(a[3]), "r"(b[0]), "r"(b[1]));
}

// ---------------- encoder ----------------
__global__ void __launch_bounds__(256) k_enc(const float* __restrict__ x,
                                             const float* __restrict__ Wenc,
                                             const float* __restrict__ benc) {
    __shared__ float sx[CC * TT];
    __shared__ float2 sW[CC * 32];
    __shared__ float2 sb[32];
    int tid = threadIdx.x, r = blockIdx.x;
    for (int i = tid; i < CC * TT; i += 256) sx[i] = x[(size_t)r * CC * TT + i];
    for (int i = tid; i < CC * 32; i += 256) {
        int c = i >> 5, l = i & 31;
        sW[i] = make_float2(Wenc[c * LL + l], Wenc[c * LL + l + 32]);
    }
    if (tid < 32) sb[tid] = make_float2(benc[tid], benc[tid + 32]);
    __syncthreads();
    int wid = tid >> 5, lane = tid & 31;
    for (int t = wid; t < TT; t += 8) {
        u64 acc = pk2(sb[lane].x, sb[lane].y);
        #pragma unroll
        for (int c = 0; c < CC; c++) {
            float xs = sx[c * TT + t];
            fma2(acc, pk2(xs, xs), pk2(sW[c * 32 + lane].x, sW[c * 32 + lane].y));
        }
        float ax, ay; upk2(acc, ax, ay);
        size_t o = ((size_t)t * NV + r) * LL;
        g_xe[o + lane] = ax;
        g_xe[o + lane + 32] = ay;
    }
}

// ---------------- fused CSR build + weight combines ----------------
__global__ void __launch_bounds__(1024) k_csr(const int* __restrict__ ei,
        const float* __restrict__ Wgd, const float* __restrict__ gdWi,
        const float* __restrict__ Wgc, const float* __restrict__ gcWi) {
    __shared__ int scnt[VV];
    __shared__ int sfil[VV];
    int tid = threadIdx.x;
    for (int i = tid; i < VV; i += 1024) { scnt[i] = 0; sfil[i] = 0; }
    __syncthreads();
    for (int e = tid; e < EE; e += 1024) atomicAdd(&scnt[ei[EE + e]], 1);
    __syncthreads();
    if (tid == 0) {
        int acc = 0;
        for (int v = 0; v < VV; v++) { g_off[v] = acc; acc += scnt[v]; }
        g_off[VV] = acc;
    }
    __syncthreads();
    for (int e = tid; e < EE; e += 1024) {
        int d = ei[EE + e];
        int p = g_off[d] + atomicAdd(&sfil[d], 1);
        g_eid[p] = e;
    }
    __syncthreads();
    for (int v = tid; v < VV; v += 1024) {
        int s = g_off[v], en = g_off[v + 1];
        for (int i = s + 1; i < en; i++) {
            int key = g_eid[i];
            int j = i - 1;
            while (j >= s && g_eid[j] > key) { g_eid[j + 1] = g_eid[j]; j--; }
            g_eid[j + 1] = key;
        }
    }
    for (int idx = tid; idx < 2 * LL * L3; idx += 1024) {
        int which = idx >= LL * L3;
        int rem = which ? idx - LL * L3 : idx;
        int k = rem / L3, j = rem - k * L3;
        const float* A = which ? Wgc : Wgd;
        const float* B = which ? gcWi : gdWi;
        float acc = 0.f;
        #pragma unroll 8
        for (int m = 0; m < LL; m++) acc = fmaf(A[k * LL + m], B[m * L3 + j], acc);
        (which ? g_Wgci : g_Wgdi)[rem] = acc;
    }
}

// ---------------- aggregation ----------------
__global__ void __launch_bounds__(256) k_agg(const int* __restrict__ ei,
                                             const float* __restrict__ attr) {
    int tid = threadIdx.x, wid = tid >> 5, lane = tid & 31;
    int gw = blockIdx.x * 8 + wid, nw = gridDim.x * 8;
    for (int task = gw; task < TT * NV; task += nw) {
        int t = task >> 14;
        int r = task & (NV - 1);
        int v = r & (VV - 1);
        const float* xb = g_xe + ((size_t)t * NV + (r & ~(VV - 1))) * LL;
        int s0 = g_off[v], s1 = g_off[v + 1];
        u64 acc = 0ULL;
        for (int e = s0; e < s1; e++) {
            int id = g_eid[e];
            int s = ei[id];
            float w = attr[id];
            float2 vv = ((const float2*)(xb + (size_t)s * LL))[lane];
            fma2(acc, pk2(w, w), pk2(vv.x, vv.y));
        }
        float a0, a1; upk2(acc, a0, a1);
        ((float2*)(g_agg + (size_t)task * LL))[lane] = make_float2(a0, a1);
    }
}

// ---------------- scan1: HMMA (mma.sync bf16 split) persistent domain GRU ----------------
// Block = 128 rows. A smem [row][128 halves: agg|h] hi/lo, row stride 68 u32.
// B smem = W^T [256 cols: z|r|ni|nh][128 halves k] hi/lo, col stride 68 u32.
#define AW 68
#define BW 68
__global__ void __launch_bounds__(256, 1) k_scan1(const float* __restrict__ Wh,
                                                  const float* __restrict__ bg) {
    extern __shared__ u32 sm1[];
    u32* Ah = sm1;                  // 128*68
    u32* Al = Ah + 128 * AW;
    u32* Bh = Al + 128 * AW;        // 256*68
    u32* Bl = Bh + 256 * BW;
    float* sb = (float*)(Bl + 256 * BW);  // 192
    int tid = threadIdx.x;
    // fill B (transposed, split, ni/nh zero-padded halves)
    for (int i = tid; i < 256 * 64; i += 256) {
        int bc = i >> 6, w = i & 63;
        int gate = bc >> 6, c = bc & 63;
        float v[2];
        #pragma unroll
        for (int e = 0; e < 2; e++) {
            int k = 2 * w + e;
            float xv;
            if (gate == 0)      xv = k < 64 ? g_Wgdi[k * L3 + c] : Wh[(k - 64) * L3 + c];
            else if (gate == 1) xv = k < 64 ? g_Wgdi[k * L3 + 64 + c] : Wh[(k - 64) * L3 + 64 + c];
            else if (gate == 2) xv = k < 64 ? g_Wgdi[k * L3 + 128 + c] : 0.f;
            else                xv = k < 64 ? 0.f : Wh[(k - 64) * L3 + 128 + c];
            v[e] = xv;
        }
        u32 h0, l0, h1, l1;
        bfsplit(v[0], h0, l0); bfsplit(v[1], h1, l1);
        Bh[bc * BW + w] = h0 | (h1 << 16);
        Bl[bc * BW + w] = l0 | (l1 << 16);
    }
    if (tid < 192) sb[tid] = bg[tid];
    // zero the h half of A
    for (int i = tid; i < 128 * 32; i += 256) {
        int row = i >> 5, w = i & 31;
        Ah[row * AW + 32 + w] = 0; Al[row * AW + 32 + w] = 0;
    }
    __syncthreads();
    int lane = tid & 31, wid = tid >> 5;
    int g = lane >> 2, tig = lane & 3;
    int rg = wid & 1, cgp = wid >> 1;
    int rowb = rg * 64;
    // bias regs per (j, e)
    float bz[2][2], br[2][2], bn[2][2];
    #pragma unroll
    for (int j = 0; j < 2; j++)
        #pragma unroll
        for (int e = 0; e < 2; e++) {
            int c = 16 * cgp + 8 * j + 2 * tig + e;
            bz[j][e] = sb[c]; br[j][e] = sb[64 + c]; bn[j][e] = sb[128 + c];
        }
    float h[4][2][4];
    #pragma unroll
    for (int mt = 0; mt < 4; mt++)
        #pragma unroll
        for (int j = 0; j < 2; j++)
            #pragma unroll
            for (int q = 0; q < 4; q++) h[mt][j][q] = 0.f;
    int srow = tid >> 1, shalf = tid & 1;
    u32 arow = srow * AW + shalf * 16;
    const float* aggb = g_agg + ((size_t)blockIdx.x * 128 + srow) * 64 + shalf * 32;
    for (int t = 0; t < TT; t++) {
        // stage agg[t] into A words 0..31
        const float2* ap = (const float2*)(aggb + (size_t)t * NV * 64);
        #pragma unroll 4
        for (int i = 0; i < 16; i++) {
            float2 xx = ap[i];
            u32 h0, l0, h1, l1;
            bfsplit(xx.x, h0, l0); bfsplit(xx.y, h1, l1);
            Ah[arow + i] = h0 | (h1 << 16);
            Al[arow + i] = l0 | (l1 << 16);
        }
        __syncthreads();
        float cz[4][2][4], cr[4][2][4], cn1[4][2][4], cn2[4][2][4];
        #pragma unroll
        for (int mt = 0; mt < 4; mt++)
            #pragma unroll
            for (int j = 0; j < 2; j++)
                #pragma unroll
                for (int q = 0; q < 4; q++) {
                    cz[mt][j][q] = 0.f; cr[mt][j][q] = 0.f;
                    cn1[mt][j][q] = 0.f; cn2[mt][j][q] = 0.f;
                }
        #pragma unroll
        for (int kt = 0; kt < 8; kt++) {
            int w0 = 8 * kt + tig, w1 = w0 + 4;
            u32 ah[4][4], al[4][4];
            #pragma unroll
            for (int mt = 0; mt < 4; mt++) {
                int r0 = rowb + mt * 16;
                ah[mt][0] = Ah[(r0 + g) * AW + w0];
                ah[mt][1] = Ah[(r0 + g + 8) * AW + w0];
                ah[mt][2] = Ah[(r0 + g) * AW + w1];
                ah[mt][3] = Ah[(r0 + g + 8) * AW + w1];
                al[mt][0] = Al[(r0 + g) * AW + w0];
                al[mt][1] = Al[(r0 + g + 8) * AW + w0];
                al[mt][2] = Al[(r0 + g) * AW + w1];
                al[mt][3] = Al[(r0 + g + 8) * AW + w1];
            }
            #pragma unroll
            for (int j = 0; j < 2; j++) {
                int cb = 16 * cgp + 8 * j + g;
                u32 bzh[2] = { Bh[cb * BW + w0], Bh[cb * BW + w1] };
                u32 bzl[2] = { Bl[cb * BW + w0], Bl[cb * BW + w1] };
                u32 brh[2] = { Bh[(64 + cb) * BW + w0], Bh[(64 + cb) * BW + w1] };
                u32 brl[2] = { Bl[(64 + cb) * BW + w0], Bl[(64 + cb) * BW + w1] };
                int nb = (kt < 4 ? 128 : 192) + cb;
                u32 bnh[2] = { Bh[nb * BW + w0], Bh[nb * BW + w1] };
                u32 bnl[2] = { Bl[nb * BW + w0], Bl[nb * BW + w1] };
                #pragma unroll
                for (int mt = 0; mt < 4; mt++) {
                    mma16816(cz[mt][j], ah[mt], bzh);
                    mma16816(cz[mt][j], ah[mt], bzl);
                    mma16816(cz[mt][j], al[mt], bzh);
                    mma16816(cr[mt][j], ah[mt], brh);
                    mma16816(cr[mt][j], ah[mt], brl);
                    mma16816(cr[mt][j], al[mt], brh);
                    float* cn = (kt < 4) ? cn1[mt][j] : cn2[mt][j];
                    mma16816(cn, ah[mt], bnh);
                    mma16816(cn, ah[mt], bnl);
                    mma16816(cn, al[mt], bnh);
                }
            }
        }
        // gates (all in regs)
        #pragma unroll
        for (int mt = 0; mt < 4; mt++)
            #pragma unroll
            for (int j = 0; j < 2; j++)
                #pragma unroll
                for (int q = 0; q < 4; q++) {
                    int e = q & 1;
                    float z = sigf(cz[mt][j][q] + bz[j][e]);
                    float r = sigf(cr[mt][j][q] + br[j][e]);
                    float n = tanh_f(cn1[mt][j][q] + bn[j][e] + r * cn2[mt][j][q]);
                    h[mt][j][q] = (1.f - z) * n + z * h[mt][j][q];
                }
        __syncthreads();
        // store h (split) into A words 32..63
        #pragma unroll
        for (int mt = 0; mt < 4; mt++) {
            int r0 = rowb + mt * 16;
            #pragma unroll
            for (int j = 0; j < 2; j++) {
                int w = 32 + 8 * cgp + 4 * j + tig;
                u32 h0, l0, h1, l1;
                bfsplit(h[mt][j][0], h0, l0); bfsplit(h[mt][j][1], h1, l1);
                Ah[(r0 + g) * AW + w] = h0 | (h1 << 16);
                Al[(r0 + g) * AW + w] = l0 | (l1 << 16);
                bfsplit(h[mt][j][2], h0, l0); bfsplit(h[mt][j][3], h1, l1);
                Ah[(r0 + g + 8) * AW + w] = h0 | (h1 << 16);
                Al[(r0 + g + 8) * AW + w] = l0 | (l1 << 16);
            }
        }
        __syncthreads();
    }
    // write h (fp32 regs) to g_hd
    #pragma unroll
    for (int mt = 0; mt < 4; mt++)
        #pragma unroll
        for (int j = 0; j < 2; j++)
            #pragma unroll
            for (int q = 0; q < 4; q++) {
                int row = rowb + mt * 16 + g + (q >> 1) * 8;
                int col = 16 * cgp + 8 * j + 2 * tig + (q & 1);
                g_hd[((size_t)blockIdx.x * 128 + row) * 64 + col] = h[mt][j][q];
            }
}

// ---------------- z_D + pre_ode ----------------
__global__ void __launch_bounds__(256) k_zd(const float* __restrict__ Wd1, const float* __restrict__ bd1,
                                            const float* __restrict__ Wd2, const float* __restrict__ bd2,
                                            const float* __restrict__ oW1, const float* __restrict__ ob1) {
    extern __shared__ u64 smz[];
    u64* sA = smz;
    u64* sB = sA + 2048;
    u64* sC = sB + 2048;
    u64* b1 = sC + 2048;
    u64* b2 = b1 + 32;
    u64* b3 = b2 + 32;
    int tid = threadIdx.x;
    for (int i = tid; i < 2048; i += 256) {
        int k = i >> 5, l = i & 31;
        sA[i] = pk2(Wd1[k * 64 + l], Wd1[k * 64 + l + 32]);
        sB[i] = pk2(Wd2[k * 64 + l], Wd2[k * 64 + l + 32]);
        sC[i] = pk2(oW1[(64 + k) * 64 + l], oW1[(64 + k) * 64 + l + 32]);
    }
    if (tid < 32) {
        b1[tid] = pk2(bd1[tid], bd1[tid + 32]);
        b2[tid] = pk2(bd2[tid], bd2[tid + 32]);
        b3[tid] = pk2(ob1[tid], ob1[tid + 32]);
    }
    __syncthreads();
    int wid = tid >> 5, lane = tid & 31;
    for (int r = blockIdx.x * 8 + wid; r < NV; r += gridDim.x * 8) {
        size_t o = (size_t)r * LL + lane;
        float2 hd = make_float2(g_hd[o], g_hd[o + 32]);
        u64 u = b1[lane];
        #pragma unroll
        for (int half = 0; half < 2; half++)
            #pragma unroll 8
            for (int kk = 0; kk < 32; kk++) {
                float hv = __shfl_sync(0xffffffffu, half ? hd.y : hd.x, kk);
                fma2(u, pk2(hv, hv), sA[(half * 32 + kk) * 32 + lane]);
            }
        float ux, uy; upk2(u, ux, uy);
        float2 uf = make_float2(tanh_f(ux), tanh_f(uy));
        u64 v = b2[lane];
        #pragma unroll
        for (int half = 0; half < 2; half++)
            #pragma unroll 8
            for (int kk = 0; kk < 32; kk++) {
                float uv = __shfl_sync(0xffffffffu, half ? uf.y : uf.x, kk);
                fma2(v, pk2(uv, uv), sB[(half * 32 + kk) * 32 + lane]);
            }
        float vx, vy; upk2(v, vx, vy);
        float2 vf = make_float2(vx, vy);
        u64 p = b3[lane];
        #pragma unroll
        for (int half = 0; half < 2; half++)
            #pragma unroll 8
            for (int kk = 0; kk < 32; kk++) {
                float vv = __shfl_sync(0xffffffffu, half ? vf.y : vf.x, kk);
                fma2(p, pk2(vv, vv), sC[(half * 32 + kk) * 32 + lane]);
            }
        float px, py; upk2(p, px, py);
        g_pre[o] = px;
        g_pre[o + 32] = py;
    }
}

// ---------------- persistent main scan (R8 structure) ----------------
__global__ void __launch_bounds__(512, 1) k_scan2(
        const float* __restrict__ Wh, const float* __restrict__ bg,
        const float* __restrict__ oW1, const float* __restrict__ oW2,
        const float* __restrict__ ob2,
        const float* __restrict__ Wdec, const float* __restrict__ bdec,
        float* __restrict__ out) {
    extern __shared__ char sms[];
    u64*   sWi  = (u64*)sms;
    u64*   sWhp = (u64*)(sms + 49152);
    u64*   sW1  = (u64*)(sms + 98304);
    u64*   sW2  = (u64*)(sms + 114688);
    float* sWdc = (float*)(sms + 131072);
    u64*   sbg  = (u64*)(sms + 135168);
    u64*   sb2  = (u64*)(sms + 135936);
    float* sbd  = (float*)(sms + 136192);
    float* srow = (float*)(sms + 136256);
    int tid = threadIdx.x;
    for (int i = tid; i < 6144; i += 512) {
        int k = i / 96, u = i - k * 96, g = u >> 5, l = u & 31;
        sWi[i]  = pk2(g_Wgci[k * L3 + g * 64 + l], g_Wgci[k * L3 + g * 64 + l + 32]);
        sWhp[i] = pk2(Wh[k * L3 + g * 64 + l], Wh[k * L3 + g * 64 + l + 32]);
    }
    for (int i = tid; i < 2048; i += 512) {
        int k = i >> 5, l = i & 31;
        sW1[i] = pk2(oW1[k * 64 + l], oW1[k * 64 + l + 32]);
        sW2[i] = pk2(oW2[k * 64 + l], oW2[k * 64 + l + 32]);
    }
    for (int i = tid; i < 1024; i += 512) sWdc[i] = Wdec[i];
    if (tid < 96) {
        int g = tid >> 5, l = tid & 31;
        sbg[tid] = pk2(bg[g * 64 + l], bg[g * 64 + l + 32]);
    }
    if (tid < 32) sb2[tid] = pk2(ob2[tid], ob2[tid + 32]);
    if (tid < 16) sbd[tid] = bdec[tid];
    __syncthreads();
    int wid = tid >> 5, lane = tid & 31;
    int c = lane & 15, hf = lane >> 4;
    for (int task = blockIdx.x * 16 + wid; task < NV / 4; task += gridDim.x * 16) {
        int r0 = task << 2;
        float2 h[4];
        u64 pre[4];
        #pragma unroll
        for (int i = 0; i < 4; i++) {
            size_t o = (size_t)(r0 + i) * LL + lane;
            h[i] = make_float2(g_xe[o], g_xe[o + 32]);
            pre[i] = pk2(g_pre[o], g_pre[o + 32]);
        }
        #pragma unroll
        for (int i = 0; i < 4; i++) {
            srow[wid * LL + lane] = h[i].x;
            srow[wid * LL + lane + 32] = h[i].y;
            __syncwarp();
            float acc = 0.f;
            #pragma unroll
            for (int j = 0; j < 32; j++) {
                int l = (hf << 5) + j;
                acc = fmaf(srow[wid * LL + l], sWdc[l * CC + c], acc);
            }
            acc += __shfl_xor_sync(0xffffffffu, acc, 16);
            if (lane < 16) out[((size_t)(r0 + i) * CC + c) * TT] = acc + sbd[c];
            __syncwarp();
        }
        for (int t = 1; t < TT; t++) {
            u64 u[4];
            #pragma unroll
            for (int i = 0; i < 4; i++) u[i] = pre[i];
            #pragma unroll
            for (int half = 0; half < 2; half++)
                #pragma unroll 8
                for (int kk = 0; kk < 32; kk++) {
                    u64 w = sW1[(half * 32 + kk) * 32 + lane];
                    #pragma unroll
                    for (int i = 0; i < 4; i++) {
                        float hv = __shfl_sync(0xffffffffu, half ? h[i].y : h[i].x, kk);
                        fma2(u[i], pk2(hv, hv), w);
                    }
                }
            float2 uf[4];
            #pragma unroll
            for (int i = 0; i < 4; i++) {
                float ux, uy; upk2(u[i], ux, uy);
                uf[i] = make_float2(tanh_f(ux), tanh_f(uy));
            }
            u64 d[4];
            #pragma unroll
            for (int i = 0; i < 4; i++) d[i] = sb2[lane];
            #pragma unroll
            for (int half = 0; half < 2; half++)
                #pragma unroll 8
                for (int kk = 0; kk < 32; kk++) {
                    u64 w = sW2[(half * 32 + kk) * 32 + lane];
                    #pragma unroll
                    for (int i = 0; i < 4; i++) {
                        float uv = __shfl_sync(0xffffffffu, half ? uf[i].y : uf[i].x, kk);
                        fma2(d[i], pk2(uv, uv), w);
                    }
                }
            float2 ho[4], a2[4];
            #pragma unroll
            for (int i = 0; i < 4; i++) {
                float dx, dy; upk2(d[i], dx, dy);
                ho[i] = make_float2(h[i].x + dx, h[i].y + dy);
                size_t o = ((size_t)t * NV + r0 + i) * LL + lane;
                a2[i] = make_float2(g_agg[o], g_agg[o + 32]);
            }
            u64 gi[4][3], gh[4][3];
            #pragma unroll
            for (int i = 0; i < 4; i++)
                #pragma unroll
                for (int g = 0; g < 3; g++) { gi[i][g] = sbg[g * 32 + lane]; gh[i][g] = 0ULL; }
            #pragma unroll
            for (int half = 0; half < 2; half++) {
                #pragma unroll 8
                for (int kk = 0; kk < 32; kk++) {
                    int k = half * 32 + kk;
                    u64 hb[4], ab[4];
                    #pragma unroll
                    for (int i = 0; i < 4; i++) {
                        float hv = __shfl_sync(0xffffffffu, half ? ho[i].y : ho[i].x, kk);
                        float av = __shfl_sync(0xffffffffu, half ? a2[i].y : a2[i].x, kk);
                        hb[i] = pk2(hv, hv);
                        ab[i] = pk2(av, av);
                    }
                    #pragma unroll
                    for (int g = 0; g < 3; g++) {
                        u64 wi = sWi[k * 96 + g * 32 + lane];
                        u64 wv = sWhp[k * 96 + g * 32 + lane];
                        #pragma unroll
                        for (int i = 0; i < 4; i++) { fma2(gi[i][g], ab[i], wi); fma2(gh[i][g], hb[i], wv); }
                    }
                }
            }
            #pragma unroll
            for (int i = 0; i < 4; i++) {
                float zx, zy, rx, ry, nix, niy, nhx, nhy;
                upk2(gi[i][0], zx, zy); upk2(gh[i][0], nix, niy);
                zx = sigf(zx + nix); zy = sigf(zy + niy);
                upk2(gi[i][1], rx, ry); upk2(gh[i][1], nix, niy);
                rx = sigf(rx + nix); ry = sigf(ry + niy);
                upk2(gi[i][2], nix, niy); upk2(gh[i][2], nhx, nhy);
                float nx = tanh_f(nix + rx * nhx), ny = tanh_f(niy + ry * nhy);
                h[i].x = (1.f - zx) * nx + zx * ho[i].x;
                h[i].y = (1.f - zy) * ny + zy * ho[i].y;
                srow[wid * LL + lane] = h[i].x;
                srow[wid * LL + lane + 32] = h[i].y;
                __syncwarp();
                float acc = 0.f;
                #pragma unroll
                for (int j = 0; j < 32; j++) {
                    int l = (hf << 5) + j;
                    acc = fmaf(srow[wid * LL + l], sWdc[l * CC + c], acc);
                }
                acc += __shfl_xor_sync(0xffffffffu, acc, 16);
                if (lane < 16) out[((size_t)(r0 + i) * CC + c) * TT + t] = acc + sbd[c];
                __syncwarp();
            }
        }
    }
}

// ---------------- launcher ----------------
extern "C" void kernel_launch(void* const* d_in, const int* in_sizes, int n_in,
                              void* d_out, int out_size) {
    const float* x    = (const float*)d_in[0];
    const int*   ei   = (const int*)d_in[1];
    const float* attr = (const float*)d_in[2];
    const float* Wenc = (const float*)d_in[3];
    const float* benc = (const float*)d_in[4];
    const float* Wgd  = (const float*)d_in[5];
    const float* gdWi = (const float*)d_in[6];
    const float* gdWh = (const float*)d_in[7];
    const float* gdb  = (const float*)d_in[8];
    const float* Wd1  = (const float*)d_in[9];
    const float* bd1  = (const float*)d_in[10];
    const float* Wd2  = (const float*)d_in[11];
    const float* bd2  = (const float*)d_in[12];
    const float* oW1  = (const float*)d_in[13];
    const float* ob1  = (const float*)d_in[14];
    const float* oW2  = (const float*)d_in[15];
    const float* ob2  = (const float*)d_in[16];
    const float* Wgc  = (const float*)d_in[17];
    const float* gcWi = (const float*)d_in[18];
    const float* gcWh = (const float*)d_in[19];
    const float* gcb  = (const float*)d_in[20];
    const float* Wdec = (const float*)d_in[21];
    const float* bdec = (const float*)d_in[22];
    float* out = (float*)d_out;

    int s1 = (2 * 128 * AW + 2 * 256 * BW) * 4 + 192 * 4;  // 209,664 B
    cudaFuncSetAttribute(k_scan1, cudaFuncAttributeMaxDynamicSharedMemorySize, s1);
    cudaFuncSetAttribute(k_zd,    cudaFuncAttributeMaxDynamicSharedMemorySize, 49920);
    cudaFuncSetAttribute(k_scan2, cudaFuncAttributeMaxDynamicSharedMemorySize, 140352);

    k_enc<<<NV, 256>>>(x, Wenc, benc);                               // 0
    k_csr<<<1, 1024>>>(ei, Wgd, gdWi, Wgc, gcWi);                    // 1
    k_agg<<<4096, 256>>>(ei, attr);                                  // 2
    k_scan1<<<128, 256, s1>>>(gdWh, gdb);                            // 3 <- ncu capture slot
    k_zd<<<128, 256, 49920>>>(Wd1, bd1, Wd2, bd2, oW1, ob1);         // 4
    k_scan2<<<148, 512, 140352>>>(gcWh, gcb, oW1, oW2, ob2, Wdec, bdec, out);  // 5
}

// round 12
// speedup vs baseline: 2.1432x; 1.7304x over previous
#include <cuda_runtime.h>
#include <cuda_bf16.h>

#define TT 150
#define VV 2048
#define CC 16
#define LL 64
#define EE 32768
#define NV 16384
#define L3 192

typedef unsigned long long u64;
typedef unsigned int u32;

__device__ float g_xe[(size_t)TT * NV * LL];
__device__ float g_agg[(size_t)TT * NV * LL];
__device__ float g_hd[NV * LL];
__device__ float g_pre[NV * LL];
__device__ float g_Wgdi[LL * L3];
__device__ float g_Wgci[LL * L3];
__device__ int   g_off[VV + 1];
__device__ int   g_eid[EE];

__device__ __forceinline__ u64 pk2(float x, float y) {
    u64 r; asm("mov.b64 %0, {%1, %2};" : "=l"(r) : "f"(x), "f"(y)); return r;
}
__device__ __forceinline__ void upk2(u64 v, float& x, float& y) {
    asm("mov.b64 {%0, %1}, %2;" : "=f"(x), "=f"(y) : "l"(v));
}
__device__ __forceinline__ void fma2(u64& d, u64 a, u64 b) {
    asm("fma.rn.f32x2 %0, %1, %2, %0;" : "+l"(d) : "l"(a), "l"(b));
}
__device__ __forceinline__ float sigf(float x) {
    x = fminf(fmaxf(x, -20.f), 20.f);
    return __fdividef(1.f, 1.f + __expf(-x));
}
__device__ __forceinline__ float tanh_f(float x) {
    x = fminf(fmaxf(x, -10.f), 10.f);
    float e = __expf(-2.f * x);
    return __fdividef(1.f - e, 1.f + e);
}
__device__ __forceinline__ void bfsplit(float x, u32& hb, u32& lb) {
    __nv_bfloat16 h = __float2bfloat16(x);
    __nv_bfloat16 l = __float2bfloat16(x - __bfloat162float(h));
    hb = (u32)__bfloat16_as_ushort(h);
    lb = (u32)__bfloat16_as_ushort(l);
}
// pack (x0 low, x1 high) hi and lo bf16x2 words in one shot
__device__ __forceinline__ void pksplit(float x0, float x1, u32& ph, u32& pl) {
    u32 hp; asm("cvt.rn.bf16x2.f32 %0, %1, %2;" : "=r"(hp) : "f"(x1), "f"(x0));
    float h0 = __uint_as_float(hp << 16);
    float h1 = __uint_as_float(hp & 0xffff0000u);
    u32 lp; asm("cvt.rn.bf16x2.f32 %0, %1, %2;" : "=r"(lp) : "f"(x1 - h1), "f"(x0 - h0));
    ph = hp; pl = lp;
}
__device__ __forceinline__ void mma16816(float* c, const u32* a, const u32* b) {
    asm volatile("mma.sync.aligned.m16n8k16.row.col.f32.bf16.bf16.f32 "
        "{%0,%1,%2,%3}, {%4,%5,%6,%7}, {%8,%9}, {%0,%1,%2,%3};"
        : "+f"(c[0]), "+f"(c[1]), "+f"(c[2]), "+f"(c[3])
        : "r"(a[0]), "r"(a[1]), "r"(a[2]), "r"(a[3]), "r"(b[0]), "r"(b[1]));
}
// A-frags (hi+lo) for k-block kt from a 16-row register tile v[8][4]
__device__ __forceinline__ void afrag(const float v[8][4], int kt, u32* ah, u32* al) {
    #pragma unroll
    for (int i = 0; i < 4; i++) {
        int j = 2 * kt + (i >> 1);
        int q0 = (i & 1) * 2;
        pksplit(v[j][q0], v[j][q0 + 1], ah[i], al[i]);
    }
}

// ---------------- encoder ----------------
__global__ void __launch_bounds__(256) k_enc(const float* __restrict__ x,
                                             const float* __restrict__ Wenc,
                                             const float* __restrict__ benc) {
    __shared__ float sx[CC * TT];
    __shared__ float2 sW[CC * 32];
    __shared__ float2 sb[32];
    int tid = threadIdx.x, r = blockIdx.x;
    for (int i = tid; i < CC * TT; i += 256) sx[i] = x[(size_t)r * CC * TT + i];
    for (int i = tid; i < CC * 32; i += 256) {
        int c = i >> 5, l = i & 31;
        sW[i] = make_float2(Wenc[c * LL + l], Wenc[c * LL + l + 32]);
    }
    if (tid < 32) sb[tid] = make_float2(benc[tid], benc[tid + 32]);
    __syncthreads();
    int wid = tid >> 5, lane = tid & 31;
    for (int t = wid; t < TT; t += 8) {
        u64 acc = pk2(sb[lane].x, sb[lane].y);
        #pragma unroll
        for (int c = 0; c < CC; c++) {
            float xs = sx[c * TT + t];
            fma2(acc, pk2(xs, xs), pk2(sW[c * 32 + lane].x, sW[c * 32 + lane].y));
        }
        float ax, ay; upk2(acc, ax, ay);
        size_t o = ((size_t)t * NV + r) * LL;
        g_xe[o + lane] = ax;
        g_xe[o + lane + 32] = ay;
    }
}

// ---------------- fused CSR build + weight combines ----------------
__global__ void __launch_bounds__(1024) k_csr(const int* __restrict__ ei,
        const float* __restrict__ Wgd, const float* __restrict__ gdWi,
        const float* __restrict__ Wgc, const float* __restrict__ gcWi) {
    __shared__ int scnt[VV];
    __shared__ int sfil[VV];
    int tid = threadIdx.x;
    for (int i = tid; i < VV; i += 1024) { scnt[i] = 0; sfil[i] = 0; }
    __syncthreads();
    for (int e = tid; e < EE; e += 1024) atomicAdd(&scnt[ei[EE + e]], 1);
    __syncthreads();
    if (tid == 0) {
        int acc = 0;
        for (int v = 0; v < VV; v++) { g_off[v] = acc; acc += scnt[v]; }
        g_off[VV] = acc;
    }
    __syncthreads();
    for (int e = tid; e < EE; e += 1024) {
        int d = ei[EE + e];
        int p = g_off[d] + atomicAdd(&sfil[d], 1);
        g_eid[p] = e;
    }
    __syncthreads();
    for (int v = tid; v < VV; v += 1024) {
        int s = g_off[v], en = g_off[v + 1];
        for (int i = s + 1; i < en; i++) {
            int key = g_eid[i];
            int j = i - 1;
            while (j >= s && g_eid[j] > key) { g_eid[j + 1] = g_eid[j]; j--; }
            g_eid[j + 1] = key;
        }
    }
    for (int idx = tid; idx < 2 * LL * L3; idx += 1024) {
        int which = idx >= LL * L3;
        int rem = which ? idx - LL * L3 : idx;
        int k = rem / L3, j = rem - k * L3;
        const float* A = which ? Wgc : Wgd;
        const float* B = which ? gcWi : gdWi;
        float acc = 0.f;
        #pragma unroll 8
        for (int m = 0; m < LL; m++) acc = fmaf(A[k * LL + m], B[m * L3 + j], acc);
        (which ? g_Wgci : g_Wgdi)[rem] = acc;
    }
}

// ---------------- aggregation ----------------
__global__ void __launch_bounds__(256) k_agg(const int* __restrict__ ei,
                                             const float* __restrict__ attr) {
    int tid = threadIdx.x, wid = tid >> 5, lane = tid & 31;
    int gw = blockIdx.x * 8 + wid, nw = gridDim.x * 8;
    for (int task = gw; task < TT * NV; task += nw) {
        int t = task >> 14;
        int r = task & (NV - 1);
        int v = r & (VV - 1);
        const float* xb = g_xe + ((size_t)t * NV + (r & ~(VV - 1))) * LL;
        int s0 = g_off[v], s1 = g_off[v + 1];
        u64 acc = 0ULL;
        for (int e = s0; e < s1; e++) {
            int id = g_eid[e];
            int s = ei[id];
            float w = attr[id];
            float2 vv = ((const float2*)(xb + (size_t)s * LL))[lane];
            fma2(acc, pk2(w, w), pk2(vv.x, vv.y));
        }
        float a0, a1; upk2(acc, a0, a1);
        ((float2*)(g_agg + (size_t)task * LL))[lane] = make_float2(a0, a1);
    }
}

// ---------------- scan1: HMMA persistent domain GRU (validated R11 version) ----------------
#define AW 68
#define BW 68
__global__ void __launch_bounds__(256, 1) k_scan1(const float* __restrict__ Wh,
                                                  const float* __restrict__ bg) {
    extern __shared__ u32 sm1[];
    u32* Ah = sm1;
    u32* Al = Ah + 128 * AW;
    u32* Bh = Al + 128 * AW;
    u32* Bl = Bh + 256 * BW;
    float* sb = (float*)(Bl + 256 * BW);
    int tid = threadIdx.x;
    for (int i = tid; i < 256 * 64; i += 256) {
        int bc = i >> 6, w = i & 63;
        int gate = bc >> 6, c = bc & 63;
        float v[2];
        #pragma unroll
        for (int e = 0; e < 2; e++) {
            int k = 2 * w + e;
            float xv;
            if (gate == 0)      xv = k < 64 ? g_Wgdi[k * L3 + c] : Wh[(k - 64) * L3 + c];
            else if (gate == 1) xv = k < 64 ? g_Wgdi[k * L3 + 64 + c] : Wh[(k - 64) * L3 + 64 + c];
            else if (gate == 2) xv = k < 64 ? g_Wgdi[k * L3 + 128 + c] : 0.f;
            else                xv = k < 64 ? 0.f : Wh[(k - 64) * L3 + 128 + c];
            v[e] = xv;
        }
        u32 h0, l0, h1, l1;
        bfsplit(v[0], h0, l0); bfsplit(v[1], h1, l1);
        Bh[bc * BW + w] = h0 | (h1 << 16);
        Bl[bc * BW + w] = l0 | (l1 << 16);
    }
    if (tid < 192) sb[tid] = bg[tid];
    for (int i = tid; i < 128 * 32; i += 256) {
        int row = i >> 5, w = i & 31;
        Ah[row * AW + 32 + w] = 0; Al[row * AW + 32 + w] = 0;
    }
    __syncthreads();
    int lane = tid & 31, wid = tid >> 5;
    int g = lane >> 2, tig = lane & 3;
    int rg = wid & 1, cgp = wid >> 1;
    int rowb = rg * 64;
    float bz[2][2], br[2][2], bn[2][2];
    #pragma unroll
    for (int j = 0; j < 2; j++)
        #pragma unroll
        for (int e = 0; e < 2; e++) {
            int c = 16 * cgp + 8 * j + 2 * tig + e;
            bz[j][e] = sb[c]; br[j][e] = sb[64 + c]; bn[j][e] = sb[128 + c];
        }
    float h[4][2][4];
    #pragma unroll
    for (int mt = 0; mt < 4; mt++)
        #pragma unroll
        for (int j = 0; j < 2; j++)
            #pragma unroll
            for (int q = 0; q < 4; q++) h[mt][j][q] = 0.f;
    int srow = tid >> 1, shalf = tid & 1;
    u32 arow = srow * AW + shalf * 16;
    const float* aggb = g_agg + ((size_t)blockIdx.x * 128 + srow) * 64 + shalf * 32;
    for (int t = 0; t < TT; t++) {
        const float2* ap = (const float2*)(aggb + (size_t)t * NV * 64);
        #pragma unroll 4
        for (int i = 0; i < 16; i++) {
            float2 xx = ap[i];
            u32 h0, l0, h1, l1;
            bfsplit(xx.x, h0, l0); bfsplit(xx.y, h1, l1);
            Ah[arow + i] = h0 | (h1 << 16);
            Al[arow + i] = l0 | (l1 << 16);
        }
        __syncthreads();
        float cz[4][2][4], cr[4][2][4], cn1[4][2][4], cn2[4][2][4];
        #pragma unroll
        for (int mt = 0; mt < 4; mt++)
            #pragma unroll
            for (int j = 0; j < 2; j++)
                #pragma unroll
                for (int q = 0; q < 4; q++) {
                    cz[mt][j][q] = 0.f; cr[mt][j][q] = 0.f;
                    cn1[mt][j][q] = 0.f; cn2[mt][j][q] = 0.f;
                }
        #pragma unroll
        for (int kt = 0; kt < 8; kt++) {
            int w0 = 8 * kt + tig, w1 = w0 + 4;
            u32 ah[4][4], al[4][4];
            #pragma unroll
            for (int mt = 0; mt < 4; mt++) {
                int r0 = rowb + mt * 16;
                ah[mt][0] = Ah[(r0 + g) * AW + w0];
                ah[mt][1] = Ah[(r0 + g + 8) * AW + w0];
                ah[mt][2] = Ah[(r0 + g) * AW + w1];
                ah[mt][3] = Ah[(r0 + g + 8) * AW + w1];
                al[mt][0] = Al[(r0 + g) * AW + w0];
                al[mt][1] = Al[(r0 + g + 8) * AW + w0];
                al[mt][2] = Al[(r0 + g) * AW + w1];
                al[mt][3] = Al[(r0 + g + 8) * AW + w1];
            }
            #pragma unroll
            for (int j = 0; j < 2; j++) {
                int cb = 16 * cgp + 8 * j + g;
                u32 bzh[2] = { Bh[cb * BW + w0], Bh[cb * BW + w1] };
                u32 bzl[2] = { Bl[cb * BW + w0], Bl[cb * BW + w1] };
                u32 brh[2] = { Bh[(64 + cb) * BW + w0], Bh[(64 + cb) * BW + w1] };
                u32 brl[2] = { Bl[(64 + cb) * BW + w0], Bl[(64 + cb) * BW + w1] };
                int nb = (kt < 4 ? 128 : 192) + cb;
                u32 bnh[2] = { Bh[nb * BW + w0], Bh[nb * BW + w1] };
                u32 bnl[2] = { Bl[nb * BW + w0], Bl[nb * BW + w1] };
                #pragma unroll
                for (int mt = 0; mt < 4; mt++) {
                    mma16816(cz[mt][j], ah[mt], bzh);
                    mma16816(cz[mt][j], ah[mt], bzl);
                    mma16816(cz[mt][j], al[mt], bzh);
                    mma16816(cr[mt][j], ah[mt], brh);
                    mma16816(cr[mt][j], ah[mt], brl);
                    mma16816(cr[mt][j], al[mt], brh);
                    float* cn = (kt < 4) ? cn1[mt][j] : cn2[mt][j];
                    mma16816(cn, ah[mt], bnh);
                    mma16816(cn, ah[mt], bnl);
                    mma16816(cn, al[mt], bnh);
                }
            }
        }
        #pragma unroll
        for (int mt = 0; mt < 4; mt++)
            #pragma unroll
            for (int j = 0; j < 2; j++)
                #pragma unroll
                for (int q = 0; q < 4; q++) {
                    int e = q & 1;
                    float z = sigf(cz[mt][j][q] + bz[j][e]);
                    float r = sigf(cr[mt][j][q] + br[j][e]);
                    float n = tanh_f(cn1[mt][j][q] + bn[j][e] + r * cn2[mt][j][q]);
                    h[mt][j][q] = (1.f - z) * n + z * h[mt][j][q];
                }
        __syncthreads();
        #pragma unroll
        for (int mt = 0; mt < 4; mt++) {
            int r0 = rowb + mt * 16;
            #pragma unroll
            for (int j = 0; j < 2; j++) {
                int w = 32 + 8 * cgp + 4 * j + tig;
                u32 h0, l0, h1, l1;
                bfsplit(h[mt][j][0], h0, l0); bfsplit(h[mt][j][1], h1, l1);
                Ah[(r0 + g) * AW + w] = h0 | (h1 << 16);
                Al[(r0 + g) * AW + w] = l0 | (l1 << 16);
                bfsplit(h[mt][j][2], h0, l0); bfsplit(h[mt][j][3], h1, l1);
                Ah[(r0 + g + 8) * AW + w] = h0 | (h1 << 16);
                Al[(r0 + g + 8) * AW + w] = l0 | (l1 << 16);
            }
        }
        __syncthreads();
    }
    #pragma unroll
    for (int mt = 0; mt < 4; mt++)
        #pragma unroll
        for (int j = 0; j < 2; j++)
            #pragma unroll
            for (int q = 0; q < 4; q++) {
                int row = rowb + mt * 16 + g + (q >> 1) * 8;
                int col = 16 * cgp + 8 * j + 2 * tig + (q & 1);
                g_hd[((size_t)blockIdx.x * 128 + row) * 64 + col] = h[mt][j][q];
            }
}

// ---------------- z_D + pre_ode ----------------
__global__ void __launch_bounds__(256) k_zd(const float* __restrict__ Wd1, const float* __restrict__ bd1,
                                            const float* __restrict__ Wd2, const float* __restrict__ bd2,
                                            const float* __restrict__ oW1, const float* __restrict__ ob1) {
    extern __shared__ u64 smz[];
    u64* sA = smz;
    u64* sB = sA + 2048;
    u64* sC = sB + 2048;
    u64* b1 = sC + 2048;
    u64* b2 = b1 + 32;
    u64* b3 = b2 + 32;
    int tid = threadIdx.x;
    for (int i = tid; i < 2048; i += 256) {
        int k = i >> 5, l = i & 31;
        sA[i] = pk2(Wd1[k * 64 + l], Wd1[k * 64 + l + 32]);
        sB[i] = pk2(Wd2[k * 64 + l], Wd2[k * 64 + l + 32]);
        sC[i] = pk2(oW1[(64 + k) * 64 + l], oW1[(64 + k) * 64 + l + 32]);
    }
    if (tid < 32) {
        b1[tid] = pk2(bd1[tid], bd1[tid + 32]);
        b2[tid] = pk2(bd2[tid], bd2[tid + 32]);
        b3[tid] = pk2(ob1[tid], ob1[tid + 32]);
    }
    __syncthreads();
    int wid = tid >> 5, lane = tid & 31;
    for (int r = blockIdx.x * 8 + wid; r < NV; r += gridDim.x * 8) {
        size_t o = (size_t)r * LL + lane;
        float2 hd = make_float2(g_hd[o], g_hd[o + 32]);
        u64 u = b1[lane];
        #pragma unroll
        for (int half = 0; half < 2; half++)
            #pragma unroll 8
            for (int kk = 0; kk < 32; kk++) {
                float hv = __shfl_sync(0xffffffffu, half ? hd.y : hd.x, kk);
                fma2(u, pk2(hv, hv), sA[(half * 32 + kk) * 32 + lane]);
            }
        float ux, uy; upk2(u, ux, uy);
        float2 uf = make_float2(tanh_f(ux), tanh_f(uy));
        u64 v = b2[lane];
        #pragma unroll
        for (int half = 0; half < 2; half++)
            #pragma unroll 8
            for (int kk = 0; kk < 32; kk++) {
                float uv = __shfl_sync(0xffffffffu, half ? uf.y : uf.x, kk);
                fma2(v, pk2(uv, uv), sB[(half * 32 + kk) * 32 + lane]);
            }
        float vx, vy; upk2(v, vx, vy);
        float2 vf = make_float2(vx, vy);
        u64 p = b3[lane];
        #pragma unroll
        for (int half = 0; half < 2; half++)
            #pragma unroll 8
            for (int kk = 0; kk < 32; kk++) {
                float vv = __shfl_sync(0xffffffffu, half ? vf.y : vf.x, kk);
                fma2(p, pk2(vv, vv), sC[(half * 32 + kk) * 32 + lane]);
            }
        float px, py; upk2(p, px, py);
        g_pre[o] = px;
        g_pre[o + 32] = py;
    }
}

// ---------------- scan2: HMMA register-chained persistent main scan ----------------
// Warp = 16 rows, fully independent. B word layout: word(8kt+2tig+e) = k-pair (16kt+2tig+8e).
__global__ void __launch_bounds__(256, 1) k_scan2(
        const float* __restrict__ Wh, const float* __restrict__ bgc,
        const float* __restrict__ oW1, const float* __restrict__ oW2,
        const float* __restrict__ ob2,
        const float* __restrict__ Wdec, const float* __restrict__ bdec,
        float* __restrict__ out) {
    extern __shared__ u32 s2[];
    u32* Bzrh = s2;                       // 128*68
    u32* Bzrl = Bzrh + 128 * 68;
    u32* Bnih = Bzrl + 128 * 68;          // 64*36 each below
    u32* Bnil = Bnih + 64 * 36;
    u32* Bnhh = Bnil + 64 * 36;
    u32* Bnhl = Bnhh + 64 * 36;
    u32* B1h  = Bnhl + 64 * 36;
    u32* B1l  = B1h + 64 * 36;
    u32* B2h  = B1l + 64 * 36;
    u32* B2l  = B2h + 64 * 36;
    u32* B4h  = B2l + 64 * 36;            // 16*36
    u32* B4l  = B4h + 16 * 36;
    float* spre = (float*)(B4l + 16 * 36); // 128*68
    float* sbg  = spre + 128 * 68;         // 192
    float* sb2  = sbg + 192;               // 64
    float* sbd  = sb2 + 64;                // 16
    int tid = threadIdx.x;
    // word index -> k-pair base: kt=w>>3, tg=(w&7)>>1, e=w&1 => k0=16kt+2tg+8e
    for (int i = tid; i < 128 * 64; i += 256) {
        int c = i >> 6, w = i & 63;
        int k0 = 16 * (w >> 3) + ((w & 7) & ~1) + 8 * (w & 1);
        float v0 = (k0 < 64) ? g_Wgci[k0 * L3 + c] : Wh[(k0 - 64) * L3 + c];
        float v1 = (k0 + 1 < 64) ? g_Wgci[(k0 + 1) * L3 + c] : Wh[(k0 + 1 - 64) * L3 + c];
        pksplit(v0, v1, Bzrh[c * 68 + w], Bzrl[c * 68 + w]);
    }
    for (int i = tid; i < 64 * 32; i += 256) {
        int c = i >> 5, w = i & 31;
        int k0 = 16 * (w >> 3) + ((w & 7) & ~1) + 8 * (w & 1);
        pksplit(g_Wgci[k0 * L3 + 128 + c], g_Wgci[(k0 + 1) * L3 + 128 + c],
                Bnih[c * 36 + w], Bnil[c * 36 + w]);
        pksplit(Wh[k0 * L3 + 128 + c], Wh[(k0 + 1) * L3 + 128 + c],
                Bnhh[c * 36 + w], Bnhl[c * 36 + w]);
        pksplit(oW1[k0 * 64 + c], oW1[(k0 + 1) * 64 + c],
                B1h[c * 36 + w], B1l[c * 36 + w]);
        pksplit(oW2[k0 * 64 + c], oW2[(k0 + 1) * 64 + c],
                B2h[c * 36 + w], B2l[c * 36 + w]);
    }
    for (int i = tid; i < 16 * 32; i += 256) {
        int c = i >> 5, w = i & 31;
        int k0 = 16 * (w >> 3) + ((w & 7) & ~1) + 8 * (w & 1);
        pksplit(Wdec[k0 * CC + c], Wdec[(k0 + 1) * CC + c],
                B4h[c * 36 + w], B4l[c * 36 + w]);
    }
    int R0b = blockIdx.x * 128;
    for (int i = tid; i < 128 * 32; i += 256) {
        int r = i >> 5, p = i & 31;
        ((float2*)spre)[r * 34 + p] = ((const float2*)(g_pre + (size_t)(R0b + r) * 64))[p];
    }
    if (tid < 192) sbg[tid] = bgc[tid];
    if (tid < 64) sb2[tid] = ob2[tid];
    if (tid < 16) sbd[tid] = bdec[tid];
    __syncthreads();

    int lane = tid & 31, wid = tid >> 5;
    int g = lane >> 2, tig = lane & 3;
    int rl = wid * 16 + g, rh = rl + 8;          // local rows
    int grl = R0b + rl, grh = R0b + rh;          // global rows
    float h[8][4];
    #pragma unroll
    for (int j = 0; j < 8; j++) {
        float2 a = *(const float2*)(g_xe + (size_t)grl * 64 + 8 * j + 2 * tig);
        float2 b = *(const float2*)(g_xe + (size_t)grh * 64 + 8 * j + 2 * tig);
        h[j][0] = a.x; h[j][1] = a.y; h[j][2] = b.x; h[j][3] = b.y;
    }
    // decode t=0
    {
        float cd[2][4] = {};
        #pragma unroll
        for (int kt = 0; kt < 4; kt++) {
            u32 ah[4], al[4]; afrag(h, kt, ah, al);
            #pragma unroll
            for (int j = 0; j < 2; j++) {
                const u32* ph = &B4h[(8 * j + g) * 36 + 8 * kt + 2 * tig];
                const u32* pl = &B4l[(8 * j + g) * 36 + 8 * kt + 2 * tig];
                u32 bh[2] = { ph[0], ph[1] }, bl[2] = { pl[0], pl[1] };
                mma16816(cd[j], ah, bh); mma16816(cd[j], ah, bl); mma16816(cd[j], al, bh);
            }
        }
        #pragma unroll
        for (int j = 0; j < 2; j++)
            #pragma unroll
            for (int q = 0; q < 4; q++) {
                int row = (q < 2) ? grl : grh;
                int col = 8 * j + 2 * tig + (q & 1);
                out[((size_t)row * CC + col) * TT] = cd[j][q] + sbd[col];
            }
    }
    for (int t = 1; t < TT; t++) {
        // R1: u = pre + h @ W1top
        float cu[8][4] = {};
        #pragma unroll
        for (int kt = 0; kt < 4; kt++) {
            u32 ah[4], al[4]; afrag(h, kt, ah, al);
            #pragma unroll
            for (int j = 0; j < 8; j++) {
                const u32* ph = &B1h[(8 * j + g) * 36 + 8 * kt + 2 * tig];
                const u32* pl = &B1l[(8 * j + g) * 36 + 8 * kt + 2 * tig];
                u32 bh[2] = { ph[0], ph[1] }, bl[2] = { pl[0], pl[1] };
                mma16816(cu[j], ah, bh); mma16816(cu[j], ah, bl); mma16816(cu[j], al, bh);
            }
        }
        float uf[8][4];
        #pragma unroll
        for (int j = 0; j < 8; j++) {
            float2 p0 = ((const float2*)spre)[rl * 34 + 4 * j + tig];
            float2 p1 = ((const float2*)spre)[rh * 34 + 4 * j + tig];
            uf[j][0] = tanh_f(cu[j][0] + p0.x); uf[j][1] = tanh_f(cu[j][1] + p0.y);
            uf[j][2] = tanh_f(cu[j][2] + p1.x); uf[j][3] = tanh_f(cu[j][3] + p1.y);
        }
        // R2: ho = h + uf @ W2 + b2
        float ho[8][4];
        {
            float cd2[8][4] = {};
            #pragma unroll
            for (int kt = 0; kt < 4; kt++) {
                u32 ah[4], al[4]; afrag(uf, kt, ah, al);
                #pragma unroll
                for (int j = 0; j < 8; j++) {
                    const u32* ph = &B2h[(8 * j + g) * 36 + 8 * kt + 2 * tig];
                    const u32* pl = &B2l[(8 * j + g) * 36 + 8 * kt + 2 * tig];
                    u32 bh[2] = { ph[0], ph[1] }, bl[2] = { pl[0], pl[1] };
                    mma16816(cd2[j], ah, bh); mma16816(cd2[j], ah, bl); mma16816(cd2[j], al, bh);
                }
            }
            #pragma unroll
            for (int j = 0; j < 8; j++)
                #pragma unroll
                for (int q = 0; q < 4; q++) {
                    int col = 8 * j + 2 * tig + (q & 1);
                    ho[j][q] = h[j][q] + cd2[j][q] + sb2[col];
                }
        }
        // R3: gates over [agg | ho]
        float cz[8][4] = {}, crr[8][4] = {}, cni[8][4] = {}, cnh[8][4] = {};
        const float* aggt = g_agg + (size_t)t * NV * 64;
        #pragma unroll
        for (int kt = 0; kt < 4; kt++) {
            float2 a0 = *(const float2*)(aggt + (size_t)grl * 64 + 16 * kt + 2 * tig);
            float2 a1 = *(const float2*)(aggt + (size_t)grh * 64 + 16 * kt + 2 * tig);
            float2 a2 = *(const float2*)(aggt + (size_t)grl * 64 + 16 * kt + 8 + 2 * tig);
            float2 a3 = *(const float2*)(aggt + (size_t)grh * 64 + 16 * kt + 8 + 2 * tig);
            u32 ah[4], al[4];
            pksplit(a0.x, a0.y, ah[0], al[0]);
            pksplit(a1.x, a1.y, ah[1], al[1]);
            pksplit(a2.x, a2.y, ah[2], al[2]);
            pksplit(a3.x, a3.y, ah[3], al[3]);
            #pragma unroll
            for (int j = 0; j < 8; j++) {
                const u32* pzh = &Bzrh[(8 * j + g) * 68 + 8 * kt + 2 * tig];
                const u32* pzl = &Bzrl[(8 * j + g) * 68 + 8 * kt + 2 * tig];
                const u32* prh = &Bzrh[(64 + 8 * j + g) * 68 + 8 * kt + 2 * tig];
                const u32* prl = &Bzrl[(64 + 8 * j + g) * 68 + 8 * kt + 2 * tig];
                const u32* pnh = &Bnih[(8 * j + g) * 36 + 8 * kt + 2 * tig];
                const u32* pnl = &Bnil[(8 * j + g) * 36 + 8 * kt + 2 * tig];
                u32 bh[2], bl[2];
                bh[0] = pzh[0]; bh[1] = pzh[1]; bl[0] = pzl[0]; bl[1] = pzl[1];
                mma16816(cz[j], ah, bh); mma16816(cz[j], ah, bl); mma16816(cz[j], al, bh);
                bh[0] = prh[0]; bh[1] = prh[1]; bl[0] = prl[0]; bl[1] = prl[1];
                mma16816(crr[j], ah, bh); mma16816(crr[j], ah, bl); mma16816(crr[j], al, bh);
                bh[0] = pnh[0]; bh[1] = pnh[1]; bl[0] = pnl[0]; bl[1] = pnl[1];
                mma16816(cni[j], ah, bh); mma16816(cni[j], ah, bl); mma16816(cni[j], al, bh);
            }
        }
        #pragma unroll
        for (int kt = 4; kt < 8; kt++) {
            u32 ah[4], al[4]; afrag(ho, kt - 4, ah, al);
            #pragma unroll
            for (int j = 0; j < 8; j++) {
                const u32* pzh = &Bzrh[(8 * j + g) * 68 + 8 * kt + 2 * tig];
                const u32* pzl = &Bzrl[(8 * j + g) * 68 + 8 * kt + 2 * tig];
                const u32* prh = &Bzrh[(64 + 8 * j + g) * 68 + 8 * kt + 2 * tig];
                const u32* prl = &Bzrl[(64 + 8 * j + g) * 68 + 8 * kt + 2 * tig];
                const u32* pnh = &Bnhh[(8 * j + g) * 36 + 8 * (kt - 4) + 2 * tig];
                const u32* pnl = &Bnhl[(8 * j + g) * 36 + 8 * (kt - 4) + 2 * tig];
                u32 bh[2], bl[2];
                bh[0] = pzh[0]; bh[1] = pzh[1]; bl[0] = pzl[0]; bl[1] = pzl[1];
                mma16816(cz[j], ah, bh); mma16816(cz[j], ah, bl); mma16816(cz[j], al, bh);
                bh[0] = prh[0]; bh[1] = prh[1]; bl[0] = prl[0]; bl[1] = prl[1];
                mma16816(crr[j], ah, bh); mma16816(crr[j], ah, bl); mma16816(crr[j], al, bh);
                bh[0] = pnh[0]; bh[1] = pnh[1]; bl[0] = pnl[0]; bl[1] = pnl[1];
                mma16816(cnh[j], ah, bh); mma16816(cnh[j], ah, bl); mma16816(cnh[j], al, bh);
            }
        }
        #pragma unroll
        for (int j = 0; j < 8; j++)
            #pragma unroll
            for (int q = 0; q < 4; q++) {
                int col = 8 * j + 2 * tig + (q & 1);
                float z = sigf(cz[j][q] + sbg[col]);
                float r = sigf(crr[j][q] + sbg[64 + col]);
                float n = tanh_f(cni[j][q] + sbg[128 + col] + r * cnh[j][q]);
                h[j][q] = (1.f - z) * n + z * ho[j][q];
            }
        // R4: decode h_t
        float cd[2][4] = {};
        #pragma unroll
        for (int kt = 0; kt < 4; kt++) {
            u32 ah[4], al[4]; afrag(h, kt, ah, al);
            #pragma unroll
            for (int j = 0; j < 2; j++) {
                const u32* ph = &B4h[(8 * j + g) * 36 + 8 * kt + 2 * tig];
                const u32* pl = &B4l[(8 * j + g) * 36 + 8 * kt + 2 * tig];
                u32 bh[2] = { ph[0], ph[1] }, bl[2] = { pl[0], pl[1] };
                mma16816(cd[j], ah, bh); mma16816(cd[j], ah, bl); mma16816(cd[j], al, bh);
            }
        }
        #pragma unroll
        for (int j = 0; j < 2; j++)
            #pragma unroll
            for (int q = 0; q < 4; q++) {
                int row = (q < 2) ? grl : grh;
                int col = 8 * j + 2 * tig + (q & 1);
                out[((size_t)row * CC + col) * TT + t] = cd[j][q] + sbd[col];
            }
    }
}

// ---------------- launcher ----------------
extern "C" void kernel_launch(void* const* d_in, const int* in_sizes, int n_in,
                              void* d_out, int out_size) {
    const float* x    = (const float*)d_in[0];
    const int*   ei   = (const int*)d_in[1];
    const float* attr = (const float*)d_in[2];
    const float* Wenc = (const float*)d_in[3];
    const float* benc = (const float*)d_in[4];
    const float* Wgd  = (const float*)d_in[5];
    const float* gdWi = (const float*)d_in[6];
    const float* gdWh = (const float*)d_in[7];
    const float* gdb  = (const float*)d_in[8];
    const float* Wd1  = (const float*)d_in[9];
    const float* bd1  = (const float*)d_in[10];
    const float* Wd2  = (const float*)d_in[11];
    const float* bd2  = (const float*)d_in[12];
    const float* oW1  = (const float*)d_in[13];
    const float* ob1  = (const float*)d_in[14];
    const float* oW2  = (const float*)d_in[15];
    const float* ob2  = (const float*)d_in[16];
    const float* Wgc  = (const float*)d_in[17];
    const float* gcWi = (const float*)d_in[18];
    const float* gcWh = (const float*)d_in[19];
    const float* gcb  = (const float*)d_in[20];
    const float* Wdec = (const float*)d_in[21];
    const float* bdec = (const float*)d_in[22];
    float* out = (float*)d_out;

    int s1 = (2 * 128 * AW + 2 * 256 * BW) * 4 + 192 * 4;
    int s2sz = (2 * 128 * 68 + 8 * 64 * 36 + 2 * 16 * 36 + 128 * 68 + 272) * 4;
    cudaFuncSetAttribute(k_scan1, cudaFuncAttributeMaxDynamicSharedMemorySize, s1);
    cudaFuncSetAttribute(k_zd,    cudaFuncAttributeMaxDynamicSharedMemorySize, 49920);
    cudaFuncSetAttribute(k_scan2, cudaFuncAttributeMaxDynamicSharedMemorySize, s2sz);

    k_enc<<<NV, 256>>>(x, Wenc, benc);                               // 0
    k_csr<<<1, 1024>>>(ei, Wgd, gdWi, Wgc, gcWi);                    // 1
    k_agg<<<4096, 256>>>(ei, attr);                                  // 2
    k_scan1<<<128, 256, s1>>>(gdWh, gdb);                            // 3
    k_zd<<<128, 256, 49920>>>(Wd1, bd1, Wd2, bd2, oW1, ob1);         // 4
    k_scan2<<<128, 256, s2sz>>>(gcWh, gcb, oW1, oW2, ob2, Wdec, bdec, out);  // 5
}

// round 13
// speedup vs baseline: 2.2667x; 1.0576x over previous
#include <cuda_runtime.h>
#include <cuda_bf16.h>

#define TT 150
#define VV 2048
#define CC 16
#define LL 64
#define EE 32768
#define NV 16384
#define L3 192

typedef unsigned long long u64;
typedef unsigned int u32;

__device__ float g_xe[(size_t)TT * NV * LL];
__device__ float g_agg[(size_t)TT * NV * LL];
__device__ float g_hd[NV * LL];
__device__ float g_pre[NV * LL];
__device__ float g_Wgdi[LL * L3];
__device__ float g_Wgci[LL * L3];
__device__ int   g_off[VV + 1];
__device__ int   g_eid[EE];
__device__ u64   g_epk[EE];

__device__ __forceinline__ u64 pk2(float x, float y) {
    u64 r; asm("mov.b64 %0, {%1, %2};" : "=l"(r) : "f"(x), "f"(y)); return r;
}
__device__ __forceinline__ void upk2(u64 v, float& x, float& y) {
    asm("mov.b64 {%0, %1}, %2;" : "=f"(x), "=f"(y) : "l"(v));
}
__device__ __forceinline__ void fma2(u64& d, u64 a, u64 b) {
    asm("fma.rn.f32x2 %0, %1, %2, %0;" : "+l"(d) : "l"(a), "l"(b));
}
__device__ __forceinline__ float sigf(float x) {
    x = fminf(fmaxf(x, -20.f), 20.f);
    return __fdividef(1.f, 1.f + __expf(-x));
}
__device__ __forceinline__ float tanh_f(float x) {
    x = fminf(fmaxf(x, -10.f), 10.f);
    float e = __expf(-2.f * x);
    return __fdividef(1.f - e, 1.f + e);
}
__device__ __forceinline__ void pksplit(float x0, float x1, u32& ph, u32& pl) {
    u32 hp; asm("cvt.rn.bf16x2.f32 %0, %1, %2;" : "=r"(hp) : "f"(x1), "f"(x0));
    float h0 = __uint_as_float(hp << 16);
    float h1 = __uint_as_float(hp & 0xffff0000u);
    u32 lp; asm("cvt.rn.bf16x2.f32 %0, %1, %2;" : "=r"(lp) : "f"(x1 - h1), "f"(x0 - h0));
    ph = hp; pl = lp;
}
__device__ __forceinline__ void mma16816(float* c, const u32* a, const u32* b) {
    asm volatile("mma.sync.aligned.m16n8k16.row.col.f32.bf16.bf16.f32 "
        "{%0,%1,%2,%3}, {%4,%5,%6,%7}, {%8,%9}, {%0,%1,%2,%3};"
        : "+f"(c[0]), "+f"(c[1]), "+f"(c[2]), "+f"(c[3])
        : "r"(a[0]), "r"(a[1]), "r"(a[2]), "r"(a[3]), "r"(b[0]), "r"(b[1]));
}
__device__ __forceinline__ void afrag(const float v[8][4], int kt, u32* ah, u32* al) {
    #pragma unroll
    for (int i = 0; i < 4; i++) {
        int j = 2 * kt + (i >> 1);
        int q0 = (i & 1) * 2;
        pksplit(v[j][q0], v[j][q0 + 1], ah[i], al[i]);
    }
}

// ---------------- encoder ----------------
__global__ void __launch_bounds__(256) k_enc(const float* __restrict__ x,
                                             const float* __restrict__ Wenc,
                                             const float* __restrict__ benc) {
    __shared__ float sx[CC * TT];
    __shared__ float2 sW[CC * 32];
    __shared__ float2 sb[32];
    int tid = threadIdx.x, r = blockIdx.x;
    for (int i = tid; i < CC * TT; i += 256) sx[i] = x[(size_t)r * CC * TT + i];
    for (int i = tid; i < CC * 32; i += 256) {
        int c = i >> 5, l = i & 31;
        sW[i] = make_float2(Wenc[c * LL + l], Wenc[c * LL + l + 32]);
    }
    if (tid < 32) sb[tid] = make_float2(benc[tid], benc[tid + 32]);
    __syncthreads();
    int wid = tid >> 5, lane = tid & 31;
    for (int t = wid; t < TT; t += 8) {
        u64 acc = pk2(sb[lane].x, sb[lane].y);
        #pragma unroll
        for (int c = 0; c < CC; c++) {
            float xs = sx[c * TT + t];
            fma2(acc, pk2(xs, xs), pk2(sW[c * 32 + lane].x, sW[c * 32 + lane].y));
        }
        float ax, ay; upk2(acc, ax, ay);
        size_t o = ((size_t)t * NV + r) * LL;
        g_xe[o + lane] = ax;
        g_xe[o + lane + 32] = ay;
    }
}

// ---------------- fused CSR build + weight combines + edge packing ----------------
__global__ void __launch_bounds__(1024) k_csr(const int* __restrict__ ei,
        const float* __restrict__ attr,
        const float* __restrict__ Wgd, const float* __restrict__ gdWi,
        const float* __restrict__ Wgc, const float* __restrict__ gcWi) {
    __shared__ int scnt[VV];
    __shared__ int sfil[VV];
    int tid = threadIdx.x;
    for (int i = tid; i < VV; i += 1024) { scnt[i] = 0; sfil[i] = 0; }
    __syncthreads();
    for (int e = tid; e < EE; e += 1024) atomicAdd(&scnt[ei[EE + e]], 1);
    __syncthreads();
    if (tid == 0) {
        int acc = 0;
        for (int v = 0; v < VV; v++) { g_off[v] = acc; acc += scnt[v]; }
        g_off[VV] = acc;
    }
    __syncthreads();
    for (int e = tid; e < EE; e += 1024) {
        int d = ei[EE + e];
        int p = g_off[d] + atomicAdd(&sfil[d], 1);
        g_eid[p] = e;
    }
    __syncthreads();
    for (int v = tid; v < VV; v += 1024) {
        int s = g_off[v], en = g_off[v + 1];
        for (int i = s + 1; i < en; i++) {
            int key = g_eid[i];
            int j = i - 1;
            while (j >= s && g_eid[j] > key) { g_eid[j + 1] = g_eid[j]; j--; }
            g_eid[j + 1] = key;
        }
    }
    __syncthreads();
    for (int p = tid; p < EE; p += 1024) {
        int e = g_eid[p];
        g_epk[p] = (u64)(u32)ei[e] | ((u64)__float_as_uint(attr[e]) << 32);
    }
    for (int idx = tid; idx < 2 * LL * L3; idx += 1024) {
        int which = idx >= LL * L3;
        int rem = which ? idx - LL * L3 : idx;
        int k = rem / L3, j = rem - k * L3;
        const float* A = which ? Wgc : Wgd;
        const float* B = which ? gcWi : gdWi;
        float acc = 0.f;
        #pragma unroll 8
        for (int m = 0; m < LL; m++) acc = fmaf(A[k * LL + m], B[m * L3 + j], acc);
        (which ? g_Wgci : g_Wgdi)[rem] = acc;
    }
}

// ---------------- aggregation (packed edges, no indirection) ----------------
__global__ void __launch_bounds__(256) k_agg() {
    int tid = threadIdx.x, wid = tid >> 5, lane = tid & 31;
    int gw = blockIdx.x * 8 + wid, nw = gridDim.x * 8;
    for (int task = gw; task < TT * NV; task += nw) {
        int t = task >> 14;
        int r = task & (NV - 1);
        int v = r & (VV - 1);
        const float* xb = g_xe + ((size_t)t * NV + (r & ~(VV - 1))) * LL;
        int s0 = g_off[v], s1 = g_off[v + 1];
        u64 acc = 0ULL;
        for (int e = s0; e < s1; e++) {
            u64 pe = g_epk[e];
            int s = (int)(u32)(pe & 0xffffffffu);
            float w = __uint_as_float((u32)(pe >> 32));
            float2 vv = ((const float2*)(xb + (size_t)s * LL))[lane];
            fma2(acc, pk2(w, w), pk2(vv.x, vv.y));
        }
        float a0, a1; upk2(acc, a0, a1);
        ((float2*)(g_agg + (size_t)task * LL))[lane] = make_float2(a0, a1);
    }
}

// ---------------- scan1: HMMA register-chained domain GRU (scan2 pattern) ----------------
__global__ void __launch_bounds__(256, 1) k_scan1(const float* __restrict__ Wh,
                                                  const float* __restrict__ bg) {
    extern __shared__ u32 s1m[];
    u32* Bzrh = s1m;                    // 128*68
    u32* Bzrl = Bzrh + 128 * 68;
    u32* Bnih = Bzrl + 128 * 68;        // 64*36
    u32* Bnil = Bnih + 64 * 36;
    u32* Bnhh = Bnil + 64 * 36;
    u32* Bnhl = Bnhh + 64 * 36;
    float* sbg = (float*)(Bnhl + 64 * 36);  // 192
    int tid = threadIdx.x;
    for (int i = tid; i < 128 * 64; i += 256) {
        int c = i >> 6, w = i & 63;
        int k0 = 16 * (w >> 3) + ((w & 7) & ~1) + 8 * (w & 1);
        float v0 = (k0 < 64) ? g_Wgdi[k0 * L3 + c] : Wh[(k0 - 64) * L3 + c];
        float v1 = (k0 + 1 < 64) ? g_Wgdi[(k0 + 1) * L3 + c] : Wh[(k0 + 1 - 64) * L3 + c];
        pksplit(v0, v1, Bzrh[c * 68 + w], Bzrl[c * 68 + w]);
    }
    for (int i = tid; i < 64 * 32; i += 256) {
        int c = i >> 5, w = i & 31;
        int k0 = 16 * (w >> 3) + ((w & 7) & ~1) + 8 * (w & 1);
        pksplit(g_Wgdi[k0 * L3 + 128 + c], g_Wgdi[(k0 + 1) * L3 + 128 + c],
                Bnih[c * 36 + w], Bnil[c * 36 + w]);
        pksplit(Wh[k0 * L3 + 128 + c], Wh[(k0 + 1) * L3 + 128 + c],
                Bnhh[c * 36 + w], Bnhl[c * 36 + w]);
    }
    if (tid < 192) sbg[tid] = bg[tid];
    __syncthreads();
    int lane = tid & 31, wid = tid >> 5;
    int g = lane >> 2, tig = lane & 3;
    int grl = blockIdx.x * 128 + wid * 16 + g, grh = grl + 8;
    float h[8][4];
    #pragma unroll
    for (int j = 0; j < 8; j++)
        #pragma unroll
        for (int q = 0; q < 4; q++) h[j][q] = 0.f;
    for (int t = 0; t < TT; t++) {
        float cz[8][4] = {}, crr[8][4] = {}, cni[8][4] = {}, cnh[8][4] = {};
        const float* aggt = g_agg + (size_t)t * NV * 64;
        #pragma unroll
        for (int kt = 0; kt < 4; kt++) {
            float2 a0 = *(const float2*)(aggt + (size_t)grl * 64 + 16 * kt + 2 * tig);
            float2 a1 = *(const float2*)(aggt + (size_t)grh * 64 + 16 * kt + 2 * tig);
            float2 a2 = *(const float2*)(aggt + (size_t)grl * 64 + 16 * kt + 8 + 2 * tig);
            float2 a3 = *(const float2*)(aggt + (size_t)grh * 64 + 16 * kt + 8 + 2 * tig);
            u32 ah[4], al[4];
            pksplit(a0.x, a0.y, ah[0], al[0]);
            pksplit(a1.x, a1.y, ah[1], al[1]);
            pksplit(a2.x, a2.y, ah[2], al[2]);
            pksplit(a3.x, a3.y, ah[3], al[3]);
            #pragma unroll
            for (int j = 0; j < 8; j++) {
                const u32* pzh = &Bzrh[(8 * j + g) * 68 + 8 * kt + 2 * tig];
                const u32* pzl = &Bzrl[(8 * j + g) * 68 + 8 * kt + 2 * tig];
                const u32* prh = &Bzrh[(64 + 8 * j + g) * 68 + 8 * kt + 2 * tig];
                const u32* prl = &Bzrl[(64 + 8 * j + g) * 68 + 8 * kt + 2 * tig];
                const u32* pnh = &Bnih[(8 * j + g) * 36 + 8 * kt + 2 * tig];
                const u32* pnl = &Bnil[(8 * j + g) * 36 + 8 * kt + 2 * tig];
                u32 bh[2], bl[2];
                bh[0] = pzh[0]; bh[1] = pzh[1]; bl[0] = pzl[0]; bl[1] = pzl[1];
                mma16816(cz[j], ah, bh); mma16816(cz[j], ah, bl); mma16816(cz[j], al, bh);
                bh[0] = prh[0]; bh[1] = prh[1]; bl[0] = prl[0]; bl[1] = prl[1];
                mma16816(crr[j], ah, bh); mma16816(crr[j], ah, bl); mma16816(crr[j], al, bh);
                bh[0] = pnh[0]; bh[1] = pnh[1]; bl[0] = pnl[0]; bl[1] = pnl[1];
                mma16816(cni[j], ah, bh); mma16816(cni[j], ah, bl); mma16816(cni[j], al, bh);
            }
        }
        #pragma unroll
        for (int kt = 4; kt < 8; kt++) {
            u32 ah[4], al[4]; afrag(h, kt - 4, ah, al);
            #pragma unroll
            for (int j = 0; j < 8; j++) {
                const u32* pzh = &Bzrh[(8 * j + g) * 68 + 8 * kt + 2 * tig];
                const u32* pzl = &Bzrl[(8 * j + g) * 68 + 8 * kt + 2 * tig];
                const u32* prh = &Bzrh[(64 + 8 * j + g) * 68 + 8 * kt + 2 * tig];
                const u32* prl = &Bzrl[(64 + 8 * j + g) * 68 + 8 * kt + 2 * tig];
                const u32* pnh = &Bnhh[(8 * j + g) * 36 + 8 * (kt - 4) + 2 * tig];
                const u32* pnl = &Bnhl[(8 * j + g) * 36 + 8 * (kt - 4) + 2 * tig];
                u32 bh[2], bl[2];
                bh[0] = pzh[0]; bh[1] = pzh[1]; bl[0] = pzl[0]; bl[1] = pzl[1];
                mma16816(cz[j], ah, bh); mma16816(cz[j], ah, bl); mma16816(cz[j], al, bh);
                bh[0] = prh[0]; bh[1] = prh[1]; bl[0] = prl[0]; bl[1] = prl[1];
                mma16816(crr[j], ah, bh); mma16816(crr[j], ah, bl); mma16816(crr[j], al, bh);
                bh[0] = pnh[0]; bh[1] = pnh[1]; bl[0] = pnl[0]; bl[1] = pnl[1];
                mma16816(cnh[j], ah, bh); mma16816(cnh[j], ah, bl); mma16816(cnh[j], al, bh);
            }
        }
        #pragma unroll
        for (int j = 0; j < 8; j++)
            #pragma unroll
            for (int q = 0; q < 4; q++) {
                int col = 8 * j + 2 * tig + (q & 1);
                float z = sigf(cz[j][q] + sbg[col]);
                float r = sigf(crr[j][q] + sbg[64 + col]);
                float n = tanh_f(cni[j][q] + sbg[128 + col] + r * cnh[j][q]);
                h[j][q] = (1.f - z) * n + z * h[j][q];
            }
    }
    #pragma unroll
    for (int j = 0; j < 8; j++)
        #pragma unroll
        for (int q = 0; q < 4; q++) {
            int row = (q < 2) ? grl : grh;
            int col = 8 * j + 2 * tig + (q & 1);
            g_hd[(size_t)row * 64 + col] = h[j][q];
        }
}

// ---------------- z_D + pre_ode ----------------
__global__ void __launch_bounds__(256) k_zd(const float* __restrict__ Wd1, const float* __restrict__ bd1,
                                            const float* __restrict__ Wd2, const float* __restrict__ bd2,
                                            const float* __restrict__ oW1, const float* __restrict__ ob1) {
    extern __shared__ u64 smz[];
    u64* sA = smz;
    u64* sB = sA + 2048;
    u64* sC = sB + 2048;
    u64* b1 = sC + 2048;
    u64* b2 = b1 + 32;
    u64* b3 = b2 + 32;
    int tid = threadIdx.x;
    for (int i = tid; i < 2048; i += 256) {
        int k = i >> 5, l = i & 31;
        sA[i] = pk2(Wd1[k * 64 + l], Wd1[k * 64 + l + 32]);
        sB[i] = pk2(Wd2[k * 64 + l], Wd2[k * 64 + l + 32]);
        sC[i] = pk2(oW1[(64 + k) * 64 + l], oW1[(64 + k) * 64 + l + 32]);
    }
    if (tid < 32) {
        b1[tid] = pk2(bd1[tid], bd1[tid + 32]);
        b2[tid] = pk2(bd2[tid], bd2[tid + 32]);
        b3[tid] = pk2(ob1[tid], ob1[tid + 32]);
    }
    __syncthreads();
    int wid = tid >> 5, lane = tid & 31;
    for (int r = blockIdx.x * 8 + wid; r < NV; r += gridDim.x * 8) {
        size_t o = (size_t)r * LL + lane;
        float2 hd = make_float2(g_hd[o], g_hd[o + 32]);
        u64 u = b1[lane];
        #pragma unroll
        for (int half = 0; half < 2; half++)
            #pragma unroll 8
            for (int kk = 0; kk < 32; kk++) {
                float hv = __shfl_sync(0xffffffffu, half ? hd.y : hd.x, kk);
                fma2(u, pk2(hv, hv), sA[(half * 32 + kk) * 32 + lane]);
            }
        float ux, uy; upk2(u, ux, uy);
        float2 uf = make_float2(tanh_f(ux), tanh_f(uy));
        u64 v = b2[lane];
        #pragma unroll
        for (int half = 0; half < 2; half++)
            #pragma unroll 8
            for (int kk = 0; kk < 32; kk++) {
                float uv = __shfl_sync(0xffffffffu, half ? uf.y : uf.x, kk);
                fma2(v, pk2(uv, uv), sB[(half * 32 + kk) * 32 + lane]);
            }
        float vx, vy; upk2(v, vx, vy);
        float2 vf = make_float2(vx, vy);
        u64 p = b3[lane];
        #pragma unroll
        for (int half = 0; half < 2; half++)
            #pragma unroll 8
            for (int kk = 0; kk < 32; kk++) {
                float vv = __shfl_sync(0xffffffffu, half ? vf.y : vf.x, kk);
                fma2(p, pk2(vv, vv), sC[(half * 32 + kk) * 32 + lane]);
            }
        float px, py; upk2(p, px, py);
        g_pre[o] = px;
        g_pre[o + 32] = py;
    }
}

// ---------------- scan2: HMMA register-chained persistent main scan (validated R12) ----------------
__global__ void __launch_bounds__(256, 1) k_scan2(
        const float* __restrict__ Wh, const float* __restrict__ bgc,
        const float* __restrict__ oW1, const float* __restrict__ oW2,
        const float* __restrict__ ob2,
        const float* __restrict__ Wdec, const float* __restrict__ bdec,
        float* __restrict__ out) {
    extern __shared__ u32 s2[];
    u32* Bzrh = s2;
    u32* Bzrl = Bzrh + 128 * 68;
    u32* Bnih = Bzrl + 128 * 68;
    u32* Bnil = Bnih + 64 * 36;
    u32* Bnhh = Bnil + 64 * 36;
    u32* Bnhl = Bnhh + 64 * 36;
    u32* B1h  = Bnhl + 64 * 36;
    u32* B1l  = B1h + 64 * 36;
    u32* B2h  = B1l + 64 * 36;
    u32* B2l  = B2h + 64 * 36;
    u32* B4h  = B2l + 64 * 36;
    u32* B4l  = B4h + 16 * 36;
    float* spre = (float*)(B4l + 16 * 36);
    float* sbg  = spre + 128 * 68;
    float* sb2  = sbg + 192;
    float* sbd  = sb2 + 64;
    int tid = threadIdx.x;
    for (int i = tid; i < 128 * 64; i += 256) {
        int c = i >> 6, w = i & 63;
        int k0 = 16 * (w >> 3) + ((w & 7) & ~1) + 8 * (w & 1);
        float v0 = (k0 < 64) ? g_Wgci[k0 * L3 + c] : Wh[(k0 - 64) * L3 + c];
        float v1 = (k0 + 1 < 64) ? g_Wgci[(k0 + 1) * L3 + c] : Wh[(k0 + 1 - 64) * L3 + c];
        pksplit(v0, v1, Bzrh[c * 68 + w], Bzrl[c * 68 + w]);
    }
    for (int i = tid; i < 64 * 32; i += 256) {
        int c = i >> 5, w = i & 31;
        int k0 = 16 * (w >> 3) + ((w & 7) & ~1) + 8 * (w & 1);
        pksplit(g_Wgci[k0 * L3 + 128 + c], g_Wgci[(k0 + 1) * L3 + 128 + c],
                Bnih[c * 36 + w], Bnil[c * 36 + w]);
        pksplit(Wh[k0 * L3 + 128 + c], Wh[(k0 + 1) * L3 + 128 + c],
                Bnhh[c * 36 + w], Bnhl[c * 36 + w]);
        pksplit(oW1[k0 * 64 + c], oW1[(k0 + 1) * 64 + c],
                B1h[c * 36 + w], B1l[c * 36 + w]);
        pksplit(oW2[k0 * 64 + c], oW2[(k0 + 1) * 64 + c],
                B2h[c * 36 + w], B2l[c * 36 + w]);
    }
    for (int i = tid; i < 16 * 32; i += 256) {
        int c = i >> 5, w = i & 31;
        int k0 = 16 * (w >> 3) + ((w & 7) & ~1) + 8 * (w & 1);
        pksplit(Wdec[k0 * CC + c], Wdec[(k0 + 1) * CC + c],
                B4h[c * 36 + w], B4l[c * 36 + w]);
    }
    int R0b = blockIdx.x * 128;
    for (int i = tid; i < 128 * 32; i += 256) {
        int r = i >> 5, p = i & 31;
        ((float2*)spre)[r * 34 + p] = ((const float2*)(g_pre + (size_t)(R0b + r) * 64))[p];
    }
    if (tid < 192) sbg[tid] = bgc[tid];
    if (tid < 64) sb2[tid] = ob2[tid];
    if (tid < 16) sbd[tid] = bdec[tid];
    __syncthreads();

    int lane = tid & 31, wid = tid >> 5;
    int g = lane >> 2, tig = lane & 3;
    int rl = wid * 16 + g, rh = rl + 8;
    int grl = R0b + rl, grh = R0b + rh;
    float h[8][4];
    #pragma unroll
    for (int j = 0; j < 8; j++) {
        float2 a = *(const float2*)(g_xe + (size_t)grl * 64 + 8 * j + 2 * tig);
        float2 b = *(const float2*)(g_xe + (size_t)grh * 64 + 8 * j + 2 * tig);
        h[j][0] = a.x; h[j][1] = a.y; h[j][2] = b.x; h[j][3] = b.y;
    }
    {
        float cd[2][4] = {};
        #pragma unroll
        for (int kt = 0; kt < 4; kt++) {
            u32 ah[4], al[4]; afrag(h, kt, ah, al);
            #pragma unroll
            for (int j = 0; j < 2; j++) {
                const u32* ph = &B4h[(8 * j + g) * 36 + 8 * kt + 2 * tig];
                const u32* pl = &B4l[(8 * j + g) * 36 + 8 * kt + 2 * tig];
                u32 bh[2] = { ph[0], ph[1] }, bl[2] = { pl[0], pl[1] };
                mma16816(cd[j], ah, bh); mma16816(cd[j], ah, bl); mma16816(cd[j], al, bh);
            }
        }
        #pragma unroll
        for (int j = 0; j < 2; j++)
            #pragma unroll
            for (int q = 0; q < 4; q++) {
                int row = (q < 2) ? grl : grh;
                int col = 8 * j + 2 * tig + (q & 1);
                out[((size_t)row * CC + col) * TT] = cd[j][q] + sbd[col];
            }
    }
    for (int t = 1; t < TT; t++) {
        float cu[8][4] = {};
        #pragma unroll
        for (int kt = 0; kt < 4; kt++) {
            u32 ah[4], al[4]; afrag(h, kt, ah, al);
            #pragma unroll
            for (int j = 0; j < 8; j++) {
                const u32* ph = &B1h[(8 * j + g) * 36 + 8 * kt + 2 * tig];
                const u32* pl = &B1l[(8 * j + g) * 36 + 8 * kt + 2 * tig];
                u32 bh[2] = { ph[0], ph[1] }, bl[2] = { pl[0], pl[1] };
                mma16816(cu[j], ah, bh); mma16816(cu[j], ah, bl); mma16816(cu[j], al, bh);
            }
        }
        float uf[8][4];
        #pragma unroll
        for (int j = 0; j < 8; j++) {
            float2 p0 = ((const float2*)spre)[rl * 34 + 4 * j + tig];
            float2 p1 = ((const float2*)spre)[rh * 34 + 4 * j + tig];
            uf[j][0] = tanh_f(cu[j][0] + p0.x); uf[j][1] = tanh_f(cu[j][1] + p0.y);
            uf[j][2] = tanh_f(cu[j][2] + p1.x); uf[j][3] = tanh_f(cu[j][3] + p1.y);
        }
        float ho[8][4];
        {
            float cd2[8][4] = {};
            #pragma unroll
            for (int kt = 0; kt < 4; kt++) {
                u32 ah[4], al[4]; afrag(uf, kt, ah, al);
                #pragma unroll
                for (int j = 0; j < 8; j++) {
                    const u32* ph = &B2h[(8 * j + g) * 36 + 8 * kt + 2 * tig];
                    const u32* pl = &B2l[(8 * j + g) * 36 + 8 * kt + 2 * tig];
                    u32 bh[2] = { ph[0], ph[1] }, bl[2] = { pl[0], pl[1] };
                    mma16816(cd2[j], ah, bh); mma16816(cd2[j], ah, bl); mma16816(cd2[j], al, bh);
                }
            }
            #pragma unroll
            for (int j = 0; j < 8; j++)
                #pragma unroll
                for (int q = 0; q < 4; q++) {
                    int col = 8 * j + 2 * tig + (q & 1);
                    ho[j][q] = h[j][q] + cd2[j][q] + sb2[col];
                }
        }
        float cz[8][4] = {}, crr[8][4] = {}, cni[8][4] = {}, cnh[8][4] = {};
        const float* aggt = g_agg + (size_t)t * NV * 64;
        #pragma unroll
        for (int kt = 0; kt < 4; kt++) {
            float2 a0 = *(const float2*)(aggt + (size_t)grl * 64 + 16 * kt + 2 * tig);
            float2 a1 = *(const float2*)(aggt + (size_t)grh * 64 + 16 * kt + 2 * tig);
            float2 a2 = *(const float2*)(aggt + (size_t)grl * 64 + 16 * kt + 8 + 2 * tig);
            float2 a3 = *(const float2*)(aggt + (size_t)grh * 64 + 16 * kt + 8 + 2 * tig);
            u32 ah[4], al[4];
            pksplit(a0.x, a0.y, ah[0], al[0]);
            pksplit(a1.x, a1.y, ah[1], al[1]);
            pksplit(a2.x, a2.y, ah[2], al[2]);
            pksplit(a3.x, a3.y, ah[3], al[3]);
            #pragma unroll
            for (int j = 0; j < 8; j++) {
                const u32* pzh = &Bzrh[(8 * j + g) * 68 + 8 * kt + 2 * tig];
                const u32* pzl = &Bzrl[(8 * j + g) * 68 + 8 * kt + 2 * tig];
                const u32* prh = &Bzrh[(64 + 8 * j + g) * 68 + 8 * kt + 2 * tig];
                const u32* prl = &Bzrl[(64 + 8 * j + g) * 68 + 8 * kt + 2 * tig];
                const u32* pnh = &Bnih[(8 * j + g) * 36 + 8 * kt + 2 * tig];
                const u32* pnl = &Bnil[(8 * j + g) * 36 + 8 * kt + 2 * tig];
                u32 bh[2], bl[2];
                bh[0] = pzh[0]; bh[1] = pzh[1]; bl[0] = pzl[0]; bl[1] = pzl[1];
                mma16816(cz[j], ah, bh); mma16816(cz[j], ah, bl); mma16816(cz[j], al, bh);
                bh[0] = prh[0]; bh[1] = prh[1]; bl[0] = prl[0]; bl[1] = prl[1];
                mma16816(crr[j], ah, bh); mma16816(crr[j], ah, bl); mma16816(crr[j], al, bh);
                bh[0] = pnh[0]; bh[1] = pnh[1]; bl[0] = pnl[0]; bl[1] = pnl[1];
                mma16816(cni[j], ah, bh); mma16816(cni[j], ah, bl); mma16816(cni[j], al, bh);
            }
        }
        #pragma unroll
        for (int kt = 4; kt < 8; kt++) {
            u32 ah[4], al[4]; afrag(ho, kt - 4, ah, al);
            #pragma unroll
            for (int j = 0; j < 8; j++) {
                const u32* pzh = &Bzrh[(8 * j + g) * 68 + 8 * kt + 2 * tig];
                const u32* pzl = &Bzrl[(8 * j + g) * 68 + 8 * kt + 2 * tig];
                const u32* prh = &Bzrh[(64 + 8 * j + g) * 68 + 8 * kt + 2 * tig];
                const u32* prl = &Bzrl[(64 + 8 * j + g) * 68 + 8 * kt + 2 * tig];
                const u32* pnh = &Bnhh[(8 * j + g) * 36 + 8 * (kt - 4) + 2 * tig];
                const u32* pnl = &Bnhl[(8 * j + g) * 36 + 8 * (kt - 4) + 2 * tig];
                u32 bh[2], bl[2];
                bh[0] = pzh[0]; bh[1] = pzh[1]; bl[0] = pzl[0]; bl[1] = pzl[1];
                mma16816(cz[j], ah, bh); mma16816(cz[j], ah, bl); mma16816(cz[j], al, bh);
                bh[0] = prh[0]; bh[1] = prh[1]; bl[0] = prl[0]; bl[1] = prl[1];
                mma16816(crr[j], ah, bh); mma16816(crr[j], ah, bl); mma16816(crr[j], al, bh);
                bh[0] = pnh[0]; bh[1] = pnh[1]; bl[0] = pnl[0]; bl[1] = pnl[1];
                mma16816(cnh[j], ah, bh); mma16816(cnh[j], ah, bl); mma16816(cnh[j], al, bh);
            }
        }
        #pragma unroll
        for (int j = 0; j < 8; j++)
            #pragma unroll
            for (int q = 0; q < 4; q++) {
                int col = 8 * j + 2 * tig + (q & 1);
                float z = sigf(cz[j][q] + sbg[col]);
                float r = sigf(crr[j][q] + sbg[64 + col]);
                float n = tanh_f(cni[j][q] + sbg[128 + col] + r * cnh[j][q]);
                h[j][q] = (1.f - z) * n + z * ho[j][q];
            }
        float cd[2][4] = {};
        #pragma unroll
        for (int kt = 0; kt < 4; kt++) {
            u32 ah[4], al[4]; afrag(h, kt, ah, al);
            #pragma unroll
            for (int j = 0; j < 2; j++) {
                const u32* ph = &B4h[(8 * j + g) * 36 + 8 * kt + 2 * tig];
                const u32* pl = &B4l[(8 * j + g) * 36 + 8 * kt + 2 * tig];
                u32 bh[2] = { ph[0], ph[1] }, bl[2] = { pl[0], pl[1] };
                mma16816(cd[j], ah, bh); mma16816(cd[j], ah, bl); mma16816(cd[j], al, bh);
            }
        }
        #pragma unroll
        for (int j = 0; j < 2; j++)
            #pragma unroll
            for (int q = 0; q < 4; q++) {
                int row = (q < 2) ? grl : grh;
                int col = 8 * j + 2 * tig + (q & 1);
                out[((size_t)row * CC + col) * TT + t] = cd[j][q] + sbd[col];
            }
    }
}

// ---------------- launcher ----------------
extern "C" void kernel_launch(void* const* d_in, const int* in_sizes, int n_in,
                              void* d_out, int out_size) {
    const float* x    = (const float*)d_in[0];
    const int*   ei   = (const int*)d_in[1];
    const float* attr = (const float*)d_in[2];
    const float* Wenc = (const float*)d_in[3];
    const float* benc = (const float*)d_in[4];
    const float* Wgd  = (const float*)d_in[5];
    const float* gdWi = (const float*)d_in[6];
    const float* gdWh = (const float*)d_in[7];
    const float* gdb  = (const float*)d_in[8];
    const float* Wd1  = (const float*)d_in[9];
    const float* bd1  = (const float*)d_in[10];
    const float* Wd2  = (const float*)d_in[11];
    const float* bd2  = (const float*)d_in[12];
    const float* oW1  = (const float*)d_in[13];
    const float* ob1  = (const float*)d_in[14];
    const float* oW2  = (const float*)d_in[15];
    const float* ob2  = (const float*)d_in[16];
    const float* Wgc  = (const float*)d_in[17];
    const float* gcWi = (const float*)d_in[18];
    const float* gcWh = (const float*)d_in[19];
    const float* gcb  = (const float*)d_in[20];
    const float* Wdec = (const float*)d_in[21];
    const float* bdec = (const float*)d_in[22];
    float* out = (float*)d_out;

    int s1sz = (2 * 128 * 68 + 4 * 64 * 36 + 192) * 4;
    int s2sz = (2 * 128 * 68 + 8 * 64 * 36 + 2 * 16 * 36 + 128 * 68 + 272) * 4;
    cudaFuncSetAttribute(k_scan1, cudaFuncAttributeMaxDynamicSharedMemorySize, s1sz);
    cudaFuncSetAttribute(k_zd,    cudaFuncAttributeMaxDynamicSharedMemorySize, 49920);
    cudaFuncSetAttribute(k_scan2, cudaFuncAttributeMaxDynamicSharedMemorySize, s2sz);

    k_enc<<<NV, 256>>>(x, Wenc, benc);                               // 0
    k_csr<<<1, 1024>>>(ei, attr, Wgd, gdWi, Wgc, gcWi);              // 1
    k_agg<<<4096, 256>>>();                                          // 2
    k_scan1<<<128, 256, s1sz>>>(gdWh, gdb);                          // 3
    k_zd<<<128, 256, 49920>>>(Wd1, bd1, Wd2, bd2, oW1, ob1);         // 4
    k_scan2<<<128, 256, s2sz>>>(gcWh, gcb, oW1, oW2, ob2, Wdec, bdec, out);  // 5
}

// round 14
// speedup vs baseline: 2.5055x; 1.1054x over previous
#include <cuda_runtime.h>
#include <cuda_bf16.h>

#define TT 150
#define VV 2048
#define CC 16
#define LL 64
#define EE 32768
#define NV 16384
#define L3 192
#define BS 72
#define NS 40

typedef unsigned long long u64;
typedef unsigned int u32;

__device__ float g_xe[(size_t)TT * NV * LL];
__device__ float g_agg[(size_t)TT * NV * LL];
__device__ float g_hd[NV * LL];
__device__ float g_pre[NV * LL];
__device__ float g_Wgdi[LL * L3];
__device__ float g_Wgci[LL * L3];
__device__ int   g_off[VV + 1];
__device__ int   g_eid[EE];
__device__ u64   g_epk[EE];

__device__ __forceinline__ u64 pk2(float x, float y) {
    u64 r; asm("mov.b64 %0, {%1, %2};" : "=l"(r) : "f"(x), "f"(y)); return r;
}
__device__ __forceinline__ void upk2(u64 v, float& x, float& y) {
    asm("mov.b64 {%0, %1}, %2;" : "=f"(x), "=f"(y) : "l"(v));
}
__device__ __forceinline__ void fma2(u64& d, u64 a, u64 b) {
    asm("fma.rn.f32x2 %0, %1, %2, %0;" : "+l"(d) : "l"(a), "l"(b));
}
__device__ __forceinline__ float sigf(float x) {
    x = fminf(fmaxf(x, -20.f), 20.f);
    return __fdividef(1.f, 1.f + __expf(-x));
}
__device__ __forceinline__ float tanh_f(float x) {
    x = fminf(fmaxf(x, -10.f), 10.f);
    float e = __expf(-2.f * x);
    return __fdividef(1.f - e, 1.f + e);
}
__device__ __forceinline__ void pksplit(float x0, float x1, u32& ph, u32& pl) {
    u32 hp; asm("cvt.rn.bf16x2.f32 %0, %1, %2;" : "=r"(hp) : "f"(x1), "f"(x0));
    float h0 = __uint_as_float(hp << 16);
    float h1 = __uint_as_float(hp & 0xffff0000u);
    u32 lp; asm("cvt.rn.bf16x2.f32 %0, %1, %2;" : "=r"(lp) : "f"(x1 - h1), "f"(x0 - h0));
    ph = hp; pl = lp;
}
__device__ __forceinline__ void mma16816(float* c, const u32* a, const u32* b) {
    asm volatile("mma.sync.aligned.m16n8k16.row.col.f32.bf16.bf16.f32 "
        "{%0,%1,%2,%3}, {%4,%5,%6,%7}, {%8,%9}, {%0,%1,%2,%3};"
        : "+f"(c[0]), "+f"(c[1]), "+f"(c[2]), "+f"(c[3])
        : "r"(a[0]), "r"(a[1]), "r"(a[2]), "r"(a[3]), "r"(b[0]), "r"(b[1]));
}
__device__ __forceinline__ void afrag(const float v[8][4], int kt, u32* ah, u32* al) {
    #pragma unroll
    for (int i = 0; i < 4; i++) {
        int j = 2 * kt + (i >> 1);
        int q0 = (i & 1) * 2;
        pksplit(v[j][q0], v[j][q0 + 1], ah[i], al[i]);
    }
}

// ---------------- encoder ----------------
__global__ void __launch_bounds__(256) k_enc(const float* __restrict__ x,
                                             const float* __restrict__ Wenc,
                                             const float* __restrict__ benc) {
    __shared__ float sx[CC * TT];
    __shared__ float2 sW[CC * 32];
    __shared__ float2 sb[32];
    int tid = threadIdx.x, r = blockIdx.x;
    for (int i = tid; i < CC * TT; i += 256) sx[i] = x[(size_t)r * CC * TT + i];
    for (int i = tid; i < CC * 32; i += 256) {
        int c = i >> 5, l = i & 31;
        sW[i] = make_float2(Wenc[c * LL + l], Wenc[c * LL + l + 32]);
    }
    if (tid < 32) sb[tid] = make_float2(benc[tid], benc[tid + 32]);
    __syncthreads();
    int wid = tid >> 5, lane = tid & 31;
    for (int t = wid; t < TT; t += 8) {
        u64 acc = pk2(sb[lane].x, sb[lane].y);
        #pragma unroll
        for (int c = 0; c < CC; c++) {
            float xs = sx[c * TT + t];
            fma2(acc, pk2(xs, xs), pk2(sW[c * 32 + lane].x, sW[c * 32 + lane].y));
        }
        float ax, ay; upk2(acc, ax, ay);
        size_t o = ((size_t)t * NV + r) * LL;
        g_xe[o + lane] = ax;
        g_xe[o + lane + 32] = ay;
    }
}

// ---------------- fused CSR build + weight combines + edge packing ----------------
__global__ void __launch_bounds__(1024) k_csr(const int* __restrict__ ei,
        const float* __restrict__ attr,
        const float* __restrict__ Wgd, const float* __restrict__ gdWi,
        const float* __restrict__ Wgc, const float* __restrict__ gcWi) {
    __shared__ int scnt[VV];
    __shared__ int sfil[VV];
    int tid = threadIdx.x;
    for (int i = tid; i < VV; i += 1024) { scnt[i] = 0; sfil[i] = 0; }
    __syncthreads();
    for (int e = tid; e < EE; e += 1024) atomicAdd(&scnt[ei[EE + e]], 1);
    __syncthreads();
    if (tid == 0) {
        int acc = 0;
        for (int v = 0; v < VV; v++) { g_off[v] = acc; acc += scnt[v]; }
        g_off[VV] = acc;
    }
    __syncthreads();
    for (int e = tid; e < EE; e += 1024) {
        int d = ei[EE + e];
        int p = g_off[d] + atomicAdd(&sfil[d], 1);
        g_eid[p] = e;
    }
    __syncthreads();
    for (int v = tid; v < VV; v += 1024) {
        int s = g_off[v], en = g_off[v + 1];
        for (int i = s + 1; i < en; i++) {
            int key = g_eid[i];
            int j = i - 1;
            while (j >= s && g_eid[j] > key) { g_eid[j + 1] = g_eid[j]; j--; }
            g_eid[j + 1] = key;
        }
    }
    __syncthreads();
    for (int p = tid; p < EE; p += 1024) {
        int e = g_eid[p];
        g_epk[p] = (u64)(u32)ei[e] | ((u64)__float_as_uint(attr[e]) << 32);
    }
    for (int idx = tid; idx < 2 * LL * L3; idx += 1024) {
        int which = idx >= LL * L3;
        int rem = which ? idx - LL * L3 : idx;
        int k = rem / L3, j = rem - k * L3;
        const float* A = which ? Wgc : Wgd;
        const float* B = which ? gcWi : gdWi;
        float acc = 0.f;
        #pragma unroll 8
        for (int m = 0; m < LL; m++) acc = fmaf(A[k * LL + m], B[m * L3 + j], acc);
        (which ? g_Wgci : g_Wgdi)[rem] = acc;
    }
}

// ---------------- aggregation (packed edges, 2x unroll for MLP) ----------------
__global__ void __launch_bounds__(256) k_agg() {
    int tid = threadIdx.x, wid = tid >> 5, lane = tid & 31;
    int gw = blockIdx.x * 8 + wid, nw = gridDim.x * 8;
    for (int task = gw; task < TT * NV; task += nw) {
        int t = task >> 14;
        int r = task & (NV - 1);
        int v = r & (VV - 1);
        const float* xb = g_xe + ((size_t)t * NV + (r & ~(VV - 1))) * LL;
        int s0 = g_off[v], s1 = g_off[v + 1];
        u64 acc = 0ULL, acc2 = 0ULL;
        int e = s0;
        for (; e + 1 < s1; e += 2) {
            u64 p0 = g_epk[e], p1 = g_epk[e + 1];
            int sA = (int)(u32)(p0 & 0xffffffffu);
            int sB = (int)(u32)(p1 & 0xffffffffu);
            float wA = __uint_as_float((u32)(p0 >> 32));
            float wB = __uint_as_float((u32)(p1 >> 32));
            float2 vA = ((const float2*)(xb + (size_t)sA * LL))[lane];
            float2 vB = ((const float2*)(xb + (size_t)sB * LL))[lane];
            fma2(acc, pk2(wA, wA), pk2(vA.x, vA.y));
            fma2(acc2, pk2(wB, wB), pk2(vB.x, vB.y));
        }
        if (e < s1) {
            u64 p0 = g_epk[e];
            int sA = (int)(u32)(p0 & 0xffffffffu);
            float wA = __uint_as_float((u32)(p0 >> 32));
            float2 vA = ((const float2*)(xb + (size_t)sA * LL))[lane];
            fma2(acc, pk2(wA, wA), pk2(vA.x, vA.y));
        }
        float a0, a1, b0, b1; upk2(acc, a0, a1); upk2(acc2, b0, b1);
        ((float2*)(g_agg + (size_t)task * LL))[lane] = make_float2(a0 + b0, a1 + b1);
    }
}

// ---------------- scan1: HMMA register-chained domain GRU ----------------
__global__ void __launch_bounds__(256, 1) k_scan1(const float* __restrict__ Wh,
                                                  const float* __restrict__ bg) {
    extern __shared__ u32 s1m[];
    u32* Bzrh = s1m;                    // 128*BS
    u32* Bzrl = Bzrh + 128 * BS;
    u32* Bnih = Bzrl + 128 * BS;        // 64*NS
    u32* Bnil = Bnih + 64 * NS;
    u32* Bnhh = Bnil + 64 * NS;
    u32* Bnhl = Bnhh + 64 * NS;
    float* sbg = (float*)(Bnhl + 64 * NS);
    int tid = threadIdx.x;
    for (int i = tid; i < 128 * 64; i += 256) {
        int c = i >> 6, w = i & 63;
        int k0 = 16 * (w >> 3) + ((w & 7) & ~1) + 8 * (w & 1);
        float v0 = (k0 < 64) ? g_Wgdi[k0 * L3 + c] : Wh[(k0 - 64) * L3 + c];
        float v1 = (k0 + 1 < 64) ? g_Wgdi[(k0 + 1) * L3 + c] : Wh[(k0 + 1 - 64) * L3 + c];
        pksplit(v0, v1, Bzrh[c * BS + w], Bzrl[c * BS + w]);
    }
    for (int i = tid; i < 64 * 32; i += 256) {
        int c = i >> 5, w = i & 31;
        int k0 = 16 * (w >> 3) + ((w & 7) & ~1) + 8 * (w & 1);
        pksplit(g_Wgdi[k0 * L3 + 128 + c], g_Wgdi[(k0 + 1) * L3 + 128 + c],
                Bnih[c * NS + w], Bnil[c * NS + w]);
        pksplit(Wh[k0 * L3 + 128 + c], Wh[(k0 + 1) * L3 + 128 + c],
                Bnhh[c * NS + w], Bnhl[c * NS + w]);
    }
    if (tid < 192) sbg[tid] = bg[tid];
    __syncthreads();
    int lane = tid & 31, wid = tid >> 5;
    int g = lane >> 2, tig = lane & 3;
    int grl = blockIdx.x * 128 + wid * 16 + g, grh = grl + 8;
    float h[8][4];
    #pragma unroll
    for (int j = 0; j < 8; j++)
        #pragma unroll
        for (int q = 0; q < 4; q++) h[j][q] = 0.f;
    for (int t = 0; t < TT; t++) {
        float cz[8][4] = {}, crr[8][4] = {}, cni[8][4] = {}, cnh[8][4] = {};
        const float* aggt = g_agg + (size_t)t * NV * 64;
        #pragma unroll
        for (int kt = 0; kt < 4; kt++) {
            float2 a0 = *(const float2*)(aggt + (size_t)grl * 64 + 16 * kt + 2 * tig);
            float2 a1 = *(const float2*)(aggt + (size_t)grh * 64 + 16 * kt + 2 * tig);
            float2 a2 = *(const float2*)(aggt + (size_t)grl * 64 + 16 * kt + 8 + 2 * tig);
            float2 a3 = *(const float2*)(aggt + (size_t)grh * 64 + 16 * kt + 8 + 2 * tig);
            u32 ah[4], al[4];
            pksplit(a0.x, a0.y, ah[0], al[0]);
            pksplit(a1.x, a1.y, ah[1], al[1]);
            pksplit(a2.x, a2.y, ah[2], al[2]);
            pksplit(a3.x, a3.y, ah[3], al[3]);
            #pragma unroll
            for (int j = 0; j < 8; j++) {
                const u32* pzh = &Bzrh[(8 * j + g) * BS + 8 * kt + 2 * tig];
                const u32* pzl = &Bzrl[(8 * j + g) * BS + 8 * kt + 2 * tig];
                const u32* prh = &Bzrh[(64 + 8 * j + g) * BS + 8 * kt + 2 * tig];
                const u32* prl = &Bzrl[(64 + 8 * j + g) * BS + 8 * kt + 2 * tig];
                const u32* pnh = &Bnih[(8 * j + g) * NS + 8 * kt + 2 * tig];
                const u32* pnl = &Bnil[(8 * j + g) * NS + 8 * kt + 2 * tig];
                u32 bh[2], bl[2];
                bh[0] = pzh[0]; bh[1] = pzh[1]; bl[0] = pzl[0]; bl[1] = pzl[1];
                mma16816(cz[j], ah, bh); mma16816(cz[j], ah, bl); mma16816(cz[j], al, bh);
                bh[0] = prh[0]; bh[1] = prh[1]; bl[0] = prl[0]; bl[1] = prl[1];
                mma16816(crr[j], ah, bh); mma16816(crr[j], ah, bl); mma16816(crr[j], al, bh);
                bh[0] = pnh[0]; bh[1] = pnh[1]; bl[0] = pnl[0]; bl[1] = pnl[1];
                mma16816(cni[j], ah, bh); mma16816(cni[j], ah, bl); mma16816(cni[j], al, bh);
            }
        }
        #pragma unroll
        for (int kt = 4; kt < 8; kt++) {
            u32 ah[4], al[4]; afrag(h, kt - 4, ah, al);
            #pragma unroll
            for (int j = 0; j < 8; j++) {
                const u32* pzh = &Bzrh[(8 * j + g) * BS + 8 * kt + 2 * tig];
                const u32* pzl = &Bzrl[(8 * j + g) * BS + 8 * kt + 2 * tig];
                const u32* prh = &Bzrh[(64 + 8 * j + g) * BS + 8 * kt + 2 * tig];
                const u32* prl = &Bzrl[(64 + 8 * j + g) * BS + 8 * kt + 2 * tig];
                const u32* pnh = &Bnhh[(8 * j + g) * NS + 8 * (kt - 4) + 2 * tig];
                const u32* pnl = &Bnhl[(8 * j + g) * NS + 8 * (kt - 4) + 2 * tig];
                u32 bh[2], bl[2];
                bh[0] = pzh[0]; bh[1] = pzh[1]; bl[0] = pzl[0]; bl[1] = pzl[1];
                mma16816(cz[j], ah, bh); mma16816(cz[j], ah, bl); mma16816(cz[j], al, bh);
                bh[0] = prh[0]; bh[1] = prh[1]; bl[0] = prl[0]; bl[1] = prl[1];
                mma16816(crr[j], ah, bh); mma16816(crr[j], ah, bl); mma16816(crr[j], al, bh);
                bh[0] = pnh[0]; bh[1] = pnh[1]; bl[0] = pnl[0]; bl[1] = pnl[1];
                mma16816(cnh[j], ah, bh); mma16816(cnh[j], ah, bl); mma16816(cnh[j], al, bh);
            }
        }
        #pragma unroll
        for (int j = 0; j < 8; j++)
            #pragma unroll
            for (int q = 0; q < 4; q++) {
                int col = 8 * j + 2 * tig + (q & 1);
                float z = sigf(cz[j][q] + sbg[col]);
                float r = sigf(crr[j][q] + sbg[64 + col]);
                float n = tanh_f(cni[j][q] + sbg[128 + col] + r * cnh[j][q]);
                h[j][q] = (1.f - z) * n + z * h[j][q];
            }
    }
    #pragma unroll
    for (int j = 0; j < 8; j++)
        #pragma unroll
        for (int q = 0; q < 4; q++) {
            int row = (q < 2) ? grl : grh;
            int col = 8 * j + 2 * tig + (q & 1);
            g_hd[(size_t)row * 64 + col] = h[j][q];
        }
}

// ---------------- z_D + pre_ode ----------------
__global__ void __launch_bounds__(256) k_zd(const float* __restrict__ Wd1, const float* __restrict__ bd1,
                                            const float* __restrict__ Wd2, const float* __restrict__ bd2,
                                            const float* __restrict__ oW1, const float* __restrict__ ob1) {
    extern __shared__ u64 smz[];
    u64* sA = smz;
    u64* sB = sA + 2048;
    u64* sC = sB + 2048;
    u64* b1 = sC + 2048;
    u64* b2 = b1 + 32;
    u64* b3 = b2 + 32;
    int tid = threadIdx.x;
    for (int i = tid; i < 2048; i += 256) {
        int k = i >> 5, l = i & 31;
        sA[i] = pk2(Wd1[k * 64 + l], Wd1[k * 64 + l + 32]);
        sB[i] = pk2(Wd2[k * 64 + l], Wd2[k * 64 + l + 32]);
        sC[i] = pk2(oW1[(64 + k) * 64 + l], oW1[(64 + k) * 64 + l + 32]);
    }
    if (tid < 32) {
        b1[tid] = pk2(bd1[tid], bd1[tid + 32]);
        b2[tid] = pk2(bd2[tid], bd2[tid + 32]);
        b3[tid] = pk2(ob1[tid], ob1[tid + 32]);
    }
    __syncthreads();
    int wid = tid >> 5, lane = tid & 31;
    for (int r = blockIdx.x * 8 + wid; r < NV; r += gridDim.x * 8) {
        size_t o = (size_t)r * LL + lane;
        float2 hd = make_float2(g_hd[o], g_hd[o + 32]);
        u64 u = b1[lane];
        #pragma unroll
        for (int half = 0; half < 2; half++)
            #pragma unroll 8
            for (int kk = 0; kk < 32; kk++) {
                float hv = __shfl_sync(0xffffffffu, half ? hd.y : hd.x, kk);
                fma2(u, pk2(hv, hv), sA[(half * 32 + kk) * 32 + lane]);
            }
        float ux, uy; upk2(u, ux, uy);
        float2 uf = make_float2(tanh_f(ux), tanh_f(uy));
        u64 v = b2[lane];
        #pragma unroll
        for (int half = 0; half < 2; half++)
            #pragma unroll 8
            for (int kk = 0; kk < 32; kk++) {
                float uv = __shfl_sync(0xffffffffu, half ? uf.y : uf.x, kk);
                fma2(v, pk2(uv, uv), sB[(half * 32 + kk) * 32 + lane]);
            }
        float vx, vy; upk2(v, vx, vy);
        float2 vf = make_float2(vx, vy);
        u64 p = b3[lane];
        #pragma unroll
        for (int half = 0; half < 2; half++)
            #pragma unroll 8
            for (int kk = 0; kk < 32; kk++) {
                float vv = __shfl_sync(0xffffffffu, half ? vf.y : vf.x, kk);
                fma2(p, pk2(vv, vv), sC[(half * 32 + kk) * 32 + lane]);
            }
        float px, py; upk2(p, px, py);
        g_pre[o] = px;
        g_pre[o + 32] = py;
    }
}

// ---------------- scan2: HMMA register-chained persistent main scan ----------------
__global__ void __launch_bounds__(256, 1) k_scan2(
        const float* __restrict__ Wh, const float* __restrict__ bgc,
        const float* __restrict__ oW1, const float* __restrict__ oW2,
        const float* __restrict__ ob2,
        const float* __restrict__ Wdec, const float* __restrict__ bdec,
        float* __restrict__ out) {
    extern __shared__ u32 s2[];
    u32* Bzrh = s2;
    u32* Bzrl = Bzrh + 128 * BS;
    u32* Bnih = Bzrl + 128 * BS;
    u32* Bnil = Bnih + 64 * NS;
    u32* Bnhh = Bnil + 64 * NS;
    u32* Bnhl = Bnhh + 64 * NS;
    u32* B1h  = Bnhl + 64 * NS;
    u32* B1l  = B1h + 64 * NS;
    u32* B2h  = B1l + 64 * NS;
    u32* B2l  = B2h + 64 * NS;
    u32* B4h  = B2l + 64 * NS;
    u32* B4l  = B4h + 16 * NS;
    float* spre = (float*)(B4l + 16 * NS);  // stride 72 floats
    float* sbg  = spre + 128 * BS;
    float* sb2  = sbg + 192;
    float* sbd  = sb2 + 64;
    int tid = threadIdx.x;
    for (int i = tid; i < 128 * 64; i += 256) {
        int c = i >> 6, w = i & 63;
        int k0 = 16 * (w >> 3) + ((w & 7) & ~1) + 8 * (w & 1);
        float v0 = (k0 < 64) ? g_Wgci[k0 * L3 + c] : Wh[(k0 - 64) * L3 + c];
        float v1 = (k0 + 1 < 64) ? g_Wgci[(k0 + 1) * L3 + c] : Wh[(k0 + 1 - 64) * L3 + c];
        pksplit(v0, v1, Bzrh[c * BS + w], Bzrl[c * BS + w]);
    }
    for (int i = tid; i < 64 * 32; i += 256) {
        int c = i >> 5, w = i & 31;
        int k0 = 16 * (w >> 3) + ((w & 7) & ~1) + 8 * (w & 1);
        pksplit(g_Wgci[k0 * L3 + 128 + c], g_Wgci[(k0 + 1) * L3 + 128 + c],
                Bnih[c * NS + w], Bnil[c * NS + w]);
        pksplit(Wh[k0 * L3 + 128 + c], Wh[(k0 + 1) * L3 + 128 + c],
                Bnhh[c * NS + w], Bnhl[c * NS + w]);
        pksplit(oW1[k0 * 64 + c], oW1[(k0 + 1) * 64 + c],
                B1h[c * NS + w], B1l[c * NS + w]);
        pksplit(oW2[k0 * 64 + c], oW2[(k0 + 1) * 64 + c],
                B2h[c * NS + w], B2l[c * NS + w]);
    }
    for (int i = tid; i < 16 * 32; i += 256) {
        int c = i >> 5, w = i & 31;
        int k0 = 16 * (w >> 3) + ((w & 7) & ~1) + 8 * (w & 1);
        pksplit(Wdec[k0 * CC + c], Wdec[(k0 + 1) * CC + c],
                B4h[c * NS + w], B4l[c * NS + w]);
    }
    int R0b = blockIdx.x * 128;
    for (int i = tid; i < 128 * 32; i += 256) {
        int r = i >> 5, p = i & 31;
        ((float2*)spre)[r * 36 + p] = ((const float2*)(g_pre + (size_t)(R0b + r) * 64))[p];
    }
    if (tid < 192) sbg[tid] = bgc[tid];
    if (tid < 64) sb2[tid] = ob2[tid];
    if (tid < 16) sbd[tid] = bdec[tid];
    __syncthreads();

    int lane = tid & 31, wid = tid >> 5;
    int g = lane >> 2, tig = lane & 3;
    int rl = wid * 16 + g, rh = rl + 8;
    int grl = R0b + rl, grh = R0b + rh;
    float h[8][4];
    #pragma unroll
    for (int j = 0; j < 8; j++) {
        float2 a = *(const float2*)(g_xe + (size_t)grl * 64 + 8 * j + 2 * tig);
        float2 b = *(const float2*)(g_xe + (size_t)grh * 64 + 8 * j + 2 * tig);
        h[j][0] = a.x; h[j][1] = a.y; h[j][2] = b.x; h[j][3] = b.y;
    }
    {
        float cd[2][4] = {};
        #pragma unroll
        for (int kt = 0; kt < 4; kt++) {
            u32 ah[4], al[4]; afrag(h, kt, ah, al);
            #pragma unroll
            for (int j = 0; j < 2; j++) {
                const u32* ph = &B4h[(8 * j + g) * NS + 8 * kt + 2 * tig];
                const u32* pl = &B4l[(8 * j + g) * NS + 8 * kt + 2 * tig];
                u32 bh[2] = { ph[0], ph[1] }, bl[2] = { pl[0], pl[1] };
                mma16816(cd[j], ah, bh); mma16816(cd[j], ah, bl); mma16816(cd[j], al, bh);
            }
        }
        #pragma unroll
        for (int j = 0; j < 2; j++)
            #pragma unroll
            for (int q = 0; q < 4; q++) {
                int row = (q < 2) ? grl : grh;
                int col = 8 * j + 2 * tig + (q & 1);
                out[((size_t)row * CC + col) * TT] = cd[j][q] + sbd[col];
            }
    }
    for (int t = 1; t < TT; t++) {
        float cu[8][4] = {};
        #pragma unroll
        for (int kt = 0; kt < 4; kt++) {
            u32 ah[4], al[4]; afrag(h, kt, ah, al);
            #pragma unroll
            for (int j = 0; j < 8; j++) {
                const u32* ph = &B1h[(8 * j + g) * NS + 8 * kt + 2 * tig];
                const u32* pl = &B1l[(8 * j + g) * NS + 8 * kt + 2 * tig];
                u32 bh[2] = { ph[0], ph[1] }, bl[2] = { pl[0], pl[1] };
                mma16816(cu[j], ah, bh); mma16816(cu[j], ah, bl); mma16816(cu[j], al, bh);
            }
        }
        float uf[8][4];
        #pragma unroll
        for (int j = 0; j < 8; j++) {
            float2 p0 = ((const float2*)spre)[rl * 36 + 4 * j + tig];
            float2 p1 = ((const float2*)spre)[rh * 36 + 4 * j + tig];
            uf[j][0] = tanh_f(cu[j][0] + p0.x); uf[j][1] = tanh_f(cu[j][1] + p0.y);
            uf[j][2] = tanh_f(cu[j][2] + p1.x); uf[j][3] = tanh_f(cu[j][3] + p1.y);
        }
        float ho[8][4];
        {
            float cd2[8][4] = {};
            #pragma unroll
            for (int kt = 0; kt < 4; kt++) {
                u32 ah[4], al[4]; afrag(uf, kt, ah, al);
                #pragma unroll
                for (int j = 0; j < 8; j++) {
                    const u32* ph = &B2h[(8 * j + g) * NS + 8 * kt + 2 * tig];
                    const u32* pl = &B2l[(8 * j + g) * NS + 8 * kt + 2 * tig];
                    u32 bh[2] = { ph[0], ph[1] }, bl[2] = { pl[0], pl[1] };
                    mma16816(cd2[j], ah, bh); mma16816(cd2[j], ah, bl); mma16816(cd2[j], al, bh);
                }
            }
            #pragma unroll
            for (int j = 0; j < 8; j++)
                #pragma unroll
                for (int q = 0; q < 4; q++) {
                    int col = 8 * j + 2 * tig + (q & 1);
                    ho[j][q] = h[j][q] + cd2[j][q] + sb2[col];
                }
        }
        float cz[8][4] = {}, crr[8][4] = {}, cni[8][4] = {}, cnh[8][4] = {};
        const float* aggt = g_agg + (size_t)t * NV * 64;
        #pragma unroll
        for (int kt = 0; kt < 4; kt++) {
            float2 a0 = *(const float2*)(aggt + (size_t)grl * 64 + 16 * kt + 2 * tig);
            float2 a1 = *(const float2*)(aggt + (size_t)grh * 64 + 16 * kt + 2 * tig);
            float2 a2 = *(const float2*)(aggt + (size_t)grl * 64 + 16 * kt + 8 + 2 * tig);
            float2 a3 = *(const float2*)(aggt + (size_t)grh * 64 + 16 * kt + 8 + 2 * tig);
            u32 ah[4], al[4];
            pksplit(a0.x, a0.y, ah[0], al[0]);
            pksplit(a1.x, a1.y, ah[1], al[1]);
            pksplit(a2.x, a2.y, ah[2], al[2]);
            pksplit(a3.x, a3.y, ah[3], al[3]);
            #pragma unroll
            for (int j = 0; j < 8; j++) {
                const u32* pzh = &Bzrh[(8 * j + g) * BS + 8 * kt + 2 * tig];
                const u32* pzl = &Bzrl[(8 * j + g) * BS + 8 * kt + 2 * tig];
                const u32* prh = &Bzrh[(64 + 8 * j + g) * BS + 8 * kt + 2 * tig];
                const u32* prl = &Bzrl[(64 + 8 * j + g) * BS + 8 * kt + 2 * tig];
                const u32* pnh = &Bnih[(8 * j + g) * NS + 8 * kt + 2 * tig];
                const u32* pnl = &Bnil[(8 * j + g) * NS + 8 * kt + 2 * tig];
                u32 bh[2], bl[2];
                bh[0] = pzh[0]; bh[1] = pzh[1]; bl[0] = pzl[0]; bl[1] = pzl[1];
                mma16816(cz[j], ah, bh); mma16816(cz[j], ah, bl); mma16816(cz[j], al, bh);
                bh[0] = prh[0]; bh[1] = prh[1]; bl[0] = prl[0]; bl[1] = prl[1];
                mma16816(crr[j], ah, bh); mma16816(crr[j], ah, bl); mma16816(crr[j], al, bh);
                bh[0] = pnh[0]; bh[1] = pnh[1]; bl[0] = pnl[0]; bl[1] = pnl[1];
                mma16816(cni[j], ah, bh); mma16816(cni[j], ah, bl); mma16816(cni[j], al, bh);
            }
        }
        #pragma unroll
        for (int kt = 4; kt < 8; kt++) {
            u32 ah[4], al[4]; afrag(ho, kt - 4, ah, al);
            #pragma unroll
            for (int j = 0; j < 8; j++) {
                const u32* pzh = &Bzrh[(8 * j + g) * BS + 8 * kt + 2 * tig];
                const u32* pzl = &Bzrl[(8 * j + g) * BS + 8 * kt + 2 * tig];
                const u32* prh = &Bzrh[(64 + 8 * j + g) * BS + 8 * kt + 2 * tig];
                const u32* prl = &Bzrl[(64 + 8 * j + g) * BS + 8 * kt + 2 * tig];
                const u32* pnh = &Bnhh[(8 * j + g) * NS + 8 * (kt - 4) + 2 * tig];
                const u32* pnl = &Bnhl[(8 * j + g) * NS + 8 * (kt - 4) + 2 * tig];
                u32 bh[2], bl[2];
                bh[0] = pzh[0]; bh[1] = pzh[1]; bl[0] = pzl[0]; bl[1] = pzl[1];
                mma16816(cz[j], ah, bh); mma16816(cz[j], ah, bl); mma16816(cz[j], al, bh);
                bh[0] = prh[0]; bh[1] = prh[1]; bl[0] = prl[0]; bl[1] = prl[1];
                mma16816(crr[j], ah, bh); mma16816(crr[j], ah, bl); mma16816(crr[j], al, bh);
                bh[0] = pnh[0]; bh[1] = pnh[1]; bl[0] = pnl[0]; bl[1] = pnl[1];
                mma16816(cnh[j], ah, bh); mma16816(cnh[j], ah, bl); mma16816(cnh[j], al, bh);
            }
        }
        #pragma unroll
        for (int j = 0; j < 8; j++)
            #pragma unroll
            for (int q = 0; q < 4; q++) {
                int col = 8 * j + 2 * tig + (q & 1);
                float z = sigf(cz[j][q] + sbg[col]);
                float r = sigf(crr[j][q] + sbg[64 + col]);
                float n = tanh_f(cni[j][q] + sbg[128 + col] + r * cnh[j][q]);
                h[j][q] = (1.f - z) * n + z * ho[j][q];
            }
        float cd[2][4] = {};
        #pragma unroll
        for (int kt = 0; kt < 4; kt++) {
            u32 ah[4], al[4]; afrag(h, kt, ah, al);
            #pragma unroll
            for (int j = 0; j < 2; j++) {
                const u32* ph = &B4h[(8 * j + g) * NS + 8 * kt + 2 * tig];
                const u32* pl = &B4l[(8 * j + g) * NS + 8 * kt + 2 * tig];
                u32 bh[2] = { ph[0], ph[1] }, bl[2] = { pl[0], pl[1] };
                mma16816(cd[j], ah, bh); mma16816(cd[j], ah, bl); mma16816(cd[j], al, bh);
            }
        }
        #pragma unroll
        for (int j = 0; j < 2; j++)
            #pragma unroll
            for (int q = 0; q < 4; q++) {
                int row = (q < 2) ? grl : grh;
                int col = 8 * j + 2 * tig + (q & 1);
                out[((size_t)row * CC + col) * TT + t] = cd[j][q] + sbd[col];
            }
    }
}

// ---------------- launcher ----------------
extern "C" void kernel_launch(void* const* d_in, const int* in_sizes, int n_in,
                              void* d_out, int out_size) {
    const float* x    = (const float*)d_in[0];
    const int*   ei   = (const int*)d_in[1];
    const float* attr = (const float*)d_in[2];
    const float* Wenc = (const float*)d_in[3];
    const float* benc = (const float*)d_in[4];
    const float* Wgd  = (const float*)d_in[5];
    const float* gdWi = (const float*)d_in[6];
    const float* gdWh = (const float*)d_in[7];
    const float* gdb  = (const float*)d_in[8];
    const float* Wd1  = (const float*)d_in[9];
    const float* bd1  = (const float*)d_in[10];
    const float* Wd2  = (const float*)d_in[11];
    const float* bd2  = (const float*)d_in[12];
    const float* oW1  = (const float*)d_in[13];
    const float* ob1  = (const float*)d_in[14];
    const float* oW2  = (const float*)d_in[15];
    const float* ob2  = (const float*)d_in[16];
    const float* Wgc  = (const float*)d_in[17];
    const float* gcWi = (const float*)d_in[18];
    const float* gcWh = (const float*)d_in[19];
    const float* gcb  = (const float*)d_in[20];
    const float* Wdec = (const float*)d_in[21];
    const float* bdec = (const float*)d_in[22];
    float* out = (float*)d_out;

    int s1sz = (2 * 128 * BS + 4 * 64 * NS + 192) * 4;
    int s2sz = (2 * 128 * BS + 8 * 64 * NS + 2 * 16 * NS + 128 * BS + 272) * 4;
    cudaFuncSetAttribute(k_scan1, cudaFuncAttributeMaxDynamicSharedMemorySize, s1sz);
    cudaFuncSetAttribute(k_zd,    cudaFuncAttributeMaxDynamicSharedMemorySize, 49920);
    cudaFuncSetAttribute(k_scan2, cudaFuncAttributeMaxDynamicSharedMemorySize, s2sz);

    k_enc<<<NV, 256>>>(x, Wenc, benc);                               // 0
    k_csr<<<1, 1024>>>(ei, attr, Wgd, gdWi, Wgc, gcWi);              // 1
    k_agg<<<4096, 256>>>();                                          // 2
    k_scan1<<<128, 256, s1sz>>>(gdWh, gdb);                          // 3
    k_zd<<<128, 256, 49920>>>(Wd1, bd1, Wd2, bd2, oW1, ob1);         // 4
    k_scan2<<<128, 256, s2sz>>>(gcWh, gcb, oW1, oW2, ob2, Wdec, bdec, out);  // 5
}